// round 5
// baseline (speedup 1.0000x reference)
#include <cuda_runtime.h>
#include <cstdint>
#include <cstdio>

#define BB 8
#define CC 32
#define HH 192
#define WW 320
#define HW (HH*WW)
#define UPH (HH/2)
#define UPW (WW/2)

// ---------------- scratch (static device globals; allocation-free) ----------------
__device__ float g_biflow[BB*4*HW];     // upsampled flow *2
__device__ float g_accA[BB*33*HW];      // splat accumulator 0 (32 ch + ones)
__device__ float g_accB[BB*33*HW];      // splat accumulator 1
__device__ float g_warp0[BB*32*HW];
__device__ float g_warp1[BB*32*HW];
__device__ float g_vol[BB*81*HW];       // leaky(correlation)
__device__ float g_h1[BB*64*HW];        // conv ping
__device__ float g_h2[BB*64*HW];        // conv pong

// ---------------- kernels ----------------

__global__ void zero_kernel(float* __restrict__ p, int n) {
    int i = blockIdx.x * blockDim.x + threadIdx.x;
    if (i < n) p[i] = 0.f;
}

// bilinear 2x upsample with half-pixel centers, edge clamp, * 2.0
__global__ void upsample_kernel(const float* __restrict__ src, float* __restrict__ dst) {
    int idx = blockIdx.x * blockDim.x + threadIdx.x;
    const int total = BB * 4 * HW;
    if (idx >= total) return;
    int x = idx % WW;
    int y = (idx / WW) % HH;
    int bc = idx / HW;
    float sx = 0.5f * x - 0.25f;
    float sy = 0.5f * y - 0.25f;
    sx = fminf(fmaxf(sx, 0.f), (float)(UPW - 1));
    sy = fminf(fmaxf(sy, 0.f), (float)(UPH - 1));
    int x0 = (int)floorf(sx);
    int y0 = (int)floorf(sy);
    float fx = sx - (float)x0;
    float fy = sy - (float)y0;
    int x1 = min(x0 + 1, UPW - 1);
    int y1 = min(y0 + 1, UPH - 1);
    const float* p = src + (size_t)bc * (UPH * UPW);
    float v00 = p[y0 * UPW + x0], v01 = p[y0 * UPW + x1];
    float v10 = p[y1 * UPW + x0], v11 = p[y1 * UPW + x1];
    float v = (1.f - fy) * ((1.f - fx) * v00 + fx * v01)
            +          fy * ((1.f - fx) * v10 + fx * v11);
    dst[idx] = 2.0f * v;
}

// forward bilinear splat of 32 channels + ones channel into acc[B,33,H,W]
__global__ void splat_kernel(const float* __restrict__ feat,
                             const float* __restrict__ flow4, int fcoff,
                             float* __restrict__ acc) {
    int idx = blockIdx.x * blockDim.x + threadIdx.x;
    const int total = BB * HW;
    if (idx >= total) return;
    int x = idx % WW;
    int y = (idx / WW) % HH;
    int b = idx / HW;
    const float* fl = flow4 + ((size_t)b * 4 + fcoff) * HW + y * WW + x;
    float fx = (float)x + fl[0];
    float fy = (float)y + fl[(size_t)HW];
    float x0f = floorf(fx), y0f = floorf(fy);
    float wx1 = fx - x0f, wy1 = fy - y0f;
    float wx0 = 1.f - wx1, wy0 = 1.f - wy1;
    int ix0 = (int)x0f, iy0 = (int)y0f;
    int ixs[4] = {ix0, ix0 + 1, ix0, ix0 + 1};
    int iys[4] = {iy0, iy0, iy0 + 1, iy0 + 1};
    float ws[4] = {wx0 * wy0, wx1 * wy0, wx0 * wy1, wx1 * wy1};
    const float* fp = feat + (size_t)b * 32 * HW + y * WW + x;
    float* ap = acc + (size_t)b * 33 * HW;
    #pragma unroll
    for (int k = 0; k < 4; ++k) {
        int ix = ixs[k], iy = iys[k];
        if (ix < 0 || ix >= WW || iy < 0 || iy >= HH) continue;
        float w = ws[k];
        int off = iy * WW + ix;
        #pragma unroll
        for (int c = 0; c < 32; ++c)
            atomicAdd(ap + (size_t)c * HW + off, fp[(size_t)c * HW] * w);
        atomicAdd(ap + (size_t)32 * HW + off, w);
    }
}

__global__ void norm_kernel(const float* __restrict__ acc, float* __restrict__ warp) {
    int idx = blockIdx.x * blockDim.x + threadIdx.x;
    const int total = BB * 32 * HW;
    if (idx >= total) return;
    int p = idx % HW;
    int c = (idx / HW) % 32;
    int b = idx / (32 * HW);
    float n = acc[((size_t)b * 33 + 32) * HW + p];
    n = (n == 0.f) ? 1.f : n;
    warp[idx] = acc[((size_t)b * 33 + c) * HW + p] / n;
}

// 9x9 local cost volume, mean over 32 ch, with leaky
__global__ void corr_kernel(const float* __restrict__ w0, const float* __restrict__ w1,
                            float* __restrict__ vol) {
    int idx = blockIdx.x * blockDim.x + threadIdx.x;
    const int total = BB * 81 * HW;
    if (idx >= total) return;
    int p = idx % HW;
    int x = p % WW, y = p / WW;
    int d = (idx / HW) % 81;
    int b = idx / (81 * HW);
    int oy = d / 9 - 4, ox = d % 9 - 4;
    int yy = y + oy, xx = x + ox;
    float s = 0.f;
    if (yy >= 0 && yy < HH && xx >= 0 && xx < WW) {
        const float* a = w0 + (size_t)b * 32 * HW + y * WW + x;
        const float* bp = w1 + (size_t)b * 32 * HW + yy * WW + xx;
        #pragma unroll
        for (int c = 0; c < 32; ++c)
            s = fmaf(a[(size_t)c * HW], bp[(size_t)c * HW], s);
        s *= (1.f / 32.f);
    }
    vol[idx] = (s >= 0.f) ? s : 0.1f * s;
}

// Direct 3x3 conv, SAME zero pad, no bias.
// Tile: 64 (x) x 16 (y) outputs per 256-thread block; each thread: 4 x-pixels x OCPB out-channels.
// Input may be a (virtual) concat of up to 3 sources.
#define TW 64
#define TH 16

template<int OCPB>
__global__ void __launch_bounds__(256)
conv3x3_kernel(const float* __restrict__ in0, int c0,
               const float* __restrict__ in1, int c1,
               const float* __restrict__ in2, int c2,
               const float* __restrict__ wts,
               float* __restrict__ out, int outC, int out_coff,
               int CIN, int nOCB, int act,
               const float* __restrict__ residual) {
    __shared__ float s_in[TH + 2][TW + 4];   // 18 x 68 (66 used, 16B-aligned rows)
    __shared__ float s_w[OCPB][12];          // 9 used, padded for float4 reads

    const int tid = threadIdx.y * 16 + threadIdx.x;
    const int bx0 = blockIdx.x * TW;
    const int by0 = blockIdx.y * TH;
    const int b   = blockIdx.z / nOCB;
    const int ocb = blockIdx.z % nOCB;
    const int ty  = threadIdx.y;
    const int txb = threadIdx.x * 4;

    float acc[OCPB][4];
    #pragma unroll
    for (int o = 0; o < OCPB; ++o)
        #pragma unroll
        for (int p = 0; p < 4; ++p) acc[o][p] = 0.f;

    for (int c = 0; c < CIN; ++c) {
        // select source plane (uniform across block)
        const float* src; int cc, sc;
        if (c < c0)            { src = in0; cc = c;            sc = c0; }
        else if (c < c0 + c1)  { src = in1; cc = c - c0;       sc = c1; }
        else                   { src = in2; cc = c - c0 - c1;  sc = c2; }
        const float* plane = src + ((size_t)b * sc + cc) * HW;

        // cooperative halo tile load (18 x 66) with zero pad
        for (int i = tid; i < 18 * 66; i += 256) {
            int r = i / 66, cl = i % 66;
            int gy = by0 + r - 1, gx = bx0 + cl - 1;
            float v = 0.f;
            if (gy >= 0 && gy < HH && gx >= 0 && gx < WW) v = plane[gy * WW + gx];
            s_in[r][cl] = v;
        }
        if (tid < OCPB * 9) {
            int oc = tid / 9, k = tid % 9;
            s_w[oc][k] = wts[((size_t)(ocb * OCPB + oc) * CIN + c) * 9 + k];
        }
        __syncthreads();

        // neighborhood registers: 3 rows x 6 cols (vectorized smem reads)
        float v[3][6];
        #pragma unroll
        for (int r = 0; r < 3; ++r) {
            float4 a4 = *reinterpret_cast<const float4*>(&s_in[ty + r][txb]);
            float2 b2 = *reinterpret_cast<const float2*>(&s_in[ty + r][txb + 4]);
            v[r][0] = a4.x; v[r][1] = a4.y; v[r][2] = a4.z; v[r][3] = a4.w;
            v[r][4] = b2.x; v[r][5] = b2.y;
        }
        #pragma unroll
        for (int oc = 0; oc < OCPB; ++oc) {
            float wr[12];
            #pragma unroll
            for (int q = 0; q < 3; ++q) {
                float4 wq = *reinterpret_cast<const float4*>(&s_w[oc][q * 4]);
                wr[q * 4 + 0] = wq.x; wr[q * 4 + 1] = wq.y;
                wr[q * 4 + 2] = wq.z; wr[q * 4 + 3] = wq.w;
            }
            #pragma unroll
            for (int ky = 0; ky < 3; ++ky)
                #pragma unroll
                for (int kx = 0; kx < 3; ++kx) {
                    float wv = wr[ky * 3 + kx];
                    #pragma unroll
                    for (int p = 0; p < 4; ++p)
                        acc[oc][p] = fmaf(v[ky][kx + p], wv, acc[oc][p]);
                }
        }
        __syncthreads();
    }

    // epilogue
    const int gy = by0 + ty;
    #pragma unroll
    for (int oc = 0; oc < OCPB; ++oc) {
        int oc_g = out_coff + ocb * OCPB + oc;
        size_t base = ((size_t)b * outC + oc_g) * HW + (size_t)gy * WW + bx0 + txb;
        #pragma unroll
        for (int p = 0; p < 4; ++p) {
            float val = acc[oc][p];
            if (act) val = (val >= 0.f) ? val : 0.1f * val;
            if (residual) val += residual[base + p];
            out[base + p] = val;
        }
    }
}

// ---------------- launch ----------------

extern "C" void kernel_launch(void* const* d_in, const int* in_sizes, int n_in,
                              void* d_out, int out_size) {
    const float* feature0 = (const float*)d_in[0];
    const float* feature1 = (const float*)d_in[1];
    const float* biflow_p = (const float*)d_in[2];
    const float* fwd_t    = (const float*)d_in[3];
    const float* bwd_t    = (const float*)d_in[4];
    const float* Wt1 = (const float*)d_in[5];
    const float* Wt2 = (const float*)d_in[6];
    const float* Wt3 = (const float*)d_in[7];
    const float* Wt4 = (const float*)d_in[8];
    const float* Wt5 = (const float*)d_in[9];
    const float* Wt6 = (const float*)d_in[10];
    const float* Wt7 = (const float*)d_in[11];
    float* out = (float*)d_out;

    float *biflow, *accA, *accB, *warp0, *warp1, *vol, *h1, *h2;
    cudaGetSymbolAddress((void**)&biflow, g_biflow);
    cudaGetSymbolAddress((void**)&accA,   g_accA);
    cudaGetSymbolAddress((void**)&accB,   g_accB);
    cudaGetSymbolAddress((void**)&warp0,  g_warp0);
    cudaGetSymbolAddress((void**)&warp1,  g_warp1);
    cudaGetSymbolAddress((void**)&vol,    g_vol);
    cudaGetSymbolAddress((void**)&h1,     g_h1);
    cudaGetSymbolAddress((void**)&h2,     g_h2);

    // 1. upsample flow
    {
        int n = BB * 4 * HW;
        upsample_kernel<<<(n + 255) / 256, 256>>>(biflow_p, biflow);
    }
    // 2. zero accumulators
    {
        int n = BB * 33 * HW;
        zero_kernel<<<(n + 255) / 256, 256>>>(accA, n);
        zero_kernel<<<(n + 255) / 256, 256>>>(accB, n);
    }
    // 3. splats
    {
        int n = BB * HW;
        splat_kernel<<<(n + 255) / 256, 256>>>(feature0, biflow, 0, accA);
        splat_kernel<<<(n + 255) / 256, 256>>>(feature1, biflow, 2, accB);
    }
    // 4. normalize
    {
        int n = BB * 32 * HW;
        norm_kernel<<<(n + 255) / 256, 256>>>(accA, warp0);
        norm_kernel<<<(n + 255) / 256, 256>>>(accB, warp1);
    }
    // 5. correlation + leaky
    {
        int n = BB * 81 * HW;
        corr_kernel<<<(n + 255) / 256, 256>>>(warp0, warp1, vol);
    }

    dim3 blk(16, 16);
    dim3 grd(WW / TW, HH / TH, 1);

    // branch forward: input concat(warp0, fwd_t, vol) -> delta_f -> out[:, 0:2]
    grd.z = BB * 8;
    conv3x3_kernel<8><<<grd, blk>>>(warp0, 32, fwd_t, 32, vol, 81, Wt1, h1, 64, 0, 145, 8, 0, nullptr);
    conv3x3_kernel<8><<<grd, blk>>>(h1, 64, nullptr, 0, nullptr, 0, Wt2, h2, 64, 0, 64, 8, 0, nullptr);
    conv3x3_kernel<8><<<grd, blk>>>(h2, 64, nullptr, 0, nullptr, 0, Wt3, h1, 64, 0, 64, 8, 1, nullptr);
    grd.z = BB * 4;
    conv3x3_kernel<8><<<grd, blk>>>(h1, 64, nullptr, 0, nullptr, 0, Wt4, h2, 32, 0, 64, 4, 0, nullptr);
    conv3x3_kernel<8><<<grd, blk>>>(h2, 32, nullptr, 0, nullptr, 0, Wt5, h1, 32, 0, 32, 4, 0, nullptr);
    grd.z = BB * 2;
    conv3x3_kernel<8><<<grd, blk>>>(h1, 32, nullptr, 0, nullptr, 0, Wt6, h2, 16, 0, 32, 2, 0, nullptr);
    grd.z = BB * 1;
    conv3x3_kernel<2><<<grd, blk>>>(h2, 16, nullptr, 0, nullptr, 0, Wt7, out, 4, 0, 16, 1, 1, biflow);

    // branch backward: input concat(warp1, bwd_t, vol) -> delta_b -> out[:, 2:4]
    grd.z = BB * 8;
    conv3x3_kernel<8><<<grd, blk>>>(warp1, 32, bwd_t, 32, vol, 81, Wt1, h1, 64, 0, 145, 8, 0, nullptr);
    conv3x3_kernel<8><<<grd, blk>>>(h1, 64, nullptr, 0, nullptr, 0, Wt2, h2, 64, 0, 64, 8, 0, nullptr);
    conv3x3_kernel<8><<<grd, blk>>>(h2, 64, nullptr, 0, nullptr, 0, Wt3, h1, 64, 0, 64, 8, 1, nullptr);
    grd.z = BB * 4;
    conv3x3_kernel<8><<<grd, blk>>>(h1, 64, nullptr, 0, nullptr, 0, Wt4, h2, 32, 0, 64, 4, 0, nullptr);
    conv3x3_kernel<8><<<grd, blk>>>(h2, 32, nullptr, 0, nullptr, 0, Wt5, h1, 32, 0, 32, 4, 0, nullptr);
    grd.z = BB * 2;
    conv3x3_kernel<8><<<grd, blk>>>(h1, 32, nullptr, 0, nullptr, 0, Wt6, h2, 16, 0, 32, 2, 0, nullptr);
    grd.z = BB * 1;
    conv3x3_kernel<2><<<grd, blk>>>(h2, 16, nullptr, 0, nullptr, 0, Wt7, out, 4, 2, 16, 1, 1, biflow);
}

// round 8
// speedup vs baseline: 1.8199x; 1.8199x over previous
#include <cuda_runtime.h>
#include <cstdint>
#include <cstdio>

#define BB 8
#define CC 32
#define HH 192
#define WW 320
#define HW (HH*WW)
#define UPH (HH/2)
#define UPW (WW/2)

// ---------------- scratch (static device globals; allocation-free) ----------------
__device__ float g_biflow[BB*4*HW];     // upsampled flow *2
__device__ float g_accA[BB*33*HW];      // splat accumulator 0 (32 ch + ones)
__device__ float g_accB[BB*33*HW];      // splat accumulator 1
__device__ float g_warp0[BB*32*HW];
__device__ float g_warp1[BB*32*HW];
__device__ float g_vol[BB*81*HW];       // leaky(correlation)
__device__ float g_h1[BB*64*HW];        // conv ping
__device__ float g_h2[BB*64*HW];        // conv pong

// ---------------- kernels ----------------

__global__ void zero_kernel(float* __restrict__ p, int n) {
    int i = blockIdx.x * blockDim.x + threadIdx.x;
    if (i < n) p[i] = 0.f;
}

// bilinear 2x upsample with half-pixel centers, edge clamp, * 2.0
__global__ void upsample_kernel(const float* __restrict__ src, float* __restrict__ dst) {
    int idx = blockIdx.x * blockDim.x + threadIdx.x;
    const int total = BB * 4 * HW;
    if (idx >= total) return;
    int x = idx % WW;
    int y = (idx / WW) % HH;
    int bc = idx / HW;
    float sx = 0.5f * x - 0.25f;
    float sy = 0.5f * y - 0.25f;
    sx = fminf(fmaxf(sx, 0.f), (float)(UPW - 1));
    sy = fminf(fmaxf(sy, 0.f), (float)(UPH - 1));
    int x0 = (int)floorf(sx);
    int y0 = (int)floorf(sy);
    float fx = sx - (float)x0;
    float fy = sy - (float)y0;
    int x1 = min(x0 + 1, UPW - 1);
    int y1 = min(y0 + 1, UPH - 1);
    const float* p = src + (size_t)bc * (UPH * UPW);
    float v00 = p[y0 * UPW + x0], v01 = p[y0 * UPW + x1];
    float v10 = p[y1 * UPW + x0], v11 = p[y1 * UPW + x1];
    float v = (1.f - fy) * ((1.f - fx) * v00 + fx * v01)
            +          fy * ((1.f - fx) * v10 + fx * v11);
    dst[idx] = 2.0f * v;
}

// forward bilinear splat of 32 channels + ones channel into acc[B,33,H,W]
__global__ void splat_kernel(const float* __restrict__ feat,
                             const float* __restrict__ flow4, int fcoff,
                             float* __restrict__ acc) {
    int idx = blockIdx.x * blockDim.x + threadIdx.x;
    const int total = BB * HW;
    if (idx >= total) return;
    int x = idx % WW;
    int y = (idx / WW) % HH;
    int b = idx / HW;
    const float* fl = flow4 + ((size_t)b * 4 + fcoff) * HW + y * WW + x;
    float fx = (float)x + fl[0];
    float fy = (float)y + fl[(size_t)HW];
    float x0f = floorf(fx), y0f = floorf(fy);
    float wx1 = fx - x0f, wy1 = fy - y0f;
    float wx0 = 1.f - wx1, wy0 = 1.f - wy1;
    int ix0 = (int)x0f, iy0 = (int)y0f;
    int ixs[4] = {ix0, ix0 + 1, ix0, ix0 + 1};
    int iys[4] = {iy0, iy0, iy0 + 1, iy0 + 1};
    float ws[4] = {wx0 * wy0, wx1 * wy0, wx0 * wy1, wx1 * wy1};
    const float* fp = feat + (size_t)b * 32 * HW + y * WW + x;
    float* ap = acc + (size_t)b * 33 * HW;
    #pragma unroll
    for (int k = 0; k < 4; ++k) {
        int ix = ixs[k], iy = iys[k];
        if (ix < 0 || ix >= WW || iy < 0 || iy >= HH) continue;
        float w = ws[k];
        int off = iy * WW + ix;
        #pragma unroll
        for (int c = 0; c < 32; ++c)
            atomicAdd(ap + (size_t)c * HW + off, fp[(size_t)c * HW] * w);
        atomicAdd(ap + (size_t)32 * HW + off, w);
    }
}

__global__ void norm_kernel(const float* __restrict__ acc, float* __restrict__ warp) {
    int idx = blockIdx.x * blockDim.x + threadIdx.x;
    const int total = BB * 32 * HW;
    if (idx >= total) return;
    int p = idx % HW;
    int c = (idx / HW) % 32;
    int b = idx / (32 * HW);
    float n = acc[((size_t)b * 33 + 32) * HW + p];
    n = (n == 0.f) ? 1.f : n;
    warp[idx] = acc[((size_t)b * 33 + c) * HW + p] / n;
}

// 9x9 local cost volume, mean over 32 ch, with leaky.
// v2: thread-per-pixel; keeps the 32 f0 channels in registers across all 81 offsets.
__global__ void __launch_bounds__(256)
corr_kernel_v2(const float* __restrict__ w0, const float* __restrict__ w1,
               float* __restrict__ vol) {
    int p = blockIdx.x * 256 + threadIdx.x;   // HW = 61440 = 240 * 256 exact
    int b = blockIdx.y;
    int x = p % WW, y = p / WW;
    const float* a0 = w0 + (size_t)b * 32 * HW + p;
    float a[32];
    #pragma unroll
    for (int c = 0; c < 32; ++c) a[c] = a0[(size_t)c * HW];
    const float* bb = w1 + (size_t)b * 32 * HW;
    float* vp = vol + (size_t)b * 81 * HW + p;
    #pragma unroll 1
    for (int dy = -4; dy <= 4; ++dy) {
        int yy = y + dy;
        #pragma unroll 1
        for (int dx = -4; dx <= 4; ++dx) {
            int xx = x + dx;
            float s = 0.f;
            if (yy >= 0 && yy < HH && xx >= 0 && xx < WW) {
                const float* bp = bb + yy * WW + xx;
                #pragma unroll
                for (int c = 0; c < 32; ++c)
                    s = fmaf(a[c], bp[(size_t)c * HW], s);
                s *= (1.f / 32.f);
            }
            *vp = (s >= 0.f) ? s : 0.1f * s;
            vp += HW;
        }
    }
}

// ------------- Direct 3x3 conv v2 -------------
// SAME zero pad, no bias. Tile 64(x) x 16(y) per 256-thread block; each thread
// 4 x-pixels x OCPB out-channels. Weights for the block's oc-slice preloaded
// into smem ONCE (padded [oc][cin][12] for float4 reads). Input tile double-
// buffered with register prefetch -> ONE __syncthreads per input channel.
#define TW 64
#define TH 16
#define NTILE (18*66)
#define NPF 5          // ceil(1188/256)

template<int OCPB>
__global__ void __launch_bounds__(256)
conv3x3_v2(const float* __restrict__ in0, int c0,
           const float* __restrict__ in1, int c1,
           const float* __restrict__ in2, int c2,
           const float* __restrict__ wts,
           float* __restrict__ out, int outC, int out_coff,
           int CIN, int nOCB, int act,
           const float* __restrict__ residual) {
    extern __shared__ float smem[];
    float* s_w  = smem;                        // [OCPB][CIN][12], k<9 valid
    float* s_in = smem + (size_t)OCPB * CIN * 12;  // [2][18][68]

    const int tid = threadIdx.y * 16 + threadIdx.x;
    const int bx0 = blockIdx.x * TW;
    const int by0 = blockIdx.y * TH;
    const int b   = blockIdx.z / nOCB;
    const int ocb = blockIdx.z % nOCB;
    const int ty  = threadIdx.y;
    const int txb = threadIdx.x * 4;

    // plane selector over (virtual) concat of up to 3 sources
    auto plane_for = [&](int c) -> const float* {
        const float* src; int cc, sc;
        if (c < c0)           { src = in0; cc = c;           sc = c0; }
        else if (c < c0 + c1) { src = in1; cc = c - c0;      sc = c1; }
        else                  { src = in2; cc = c - c0 - c1; sc = c2; }
        return src + ((size_t)b * sc + cc) * HW;
    };

    // ---- one-time weight preload: wts[ocb*OCPB+oc][cin][9] -> s_w[oc][cin][12]
    for (int i = tid; i < OCPB * CIN * 9; i += 256) {
        int oc = i / (CIN * 9);
        int r  = i % (CIN * 9);
        int ci = r / 9, k = r % 9;
        s_w[((size_t)oc * CIN + ci) * 12 + k] =
            wts[((size_t)(ocb * OCPB + oc) * CIN + ci) * 9 + k];
    }
    // ---- load channel 0 tile into buffer 0
    {
        const float* plane = plane_for(0);
        for (int i = tid; i < NTILE; i += 256) {
            int r = i / 66, cl = i % 66;
            int gy = by0 + r - 1, gx = bx0 + cl - 1;
            float v = 0.f;
            if ((unsigned)gy < HH && (unsigned)gx < WW) v = plane[gy * WW + gx];
            s_in[(size_t)r * 68 + cl] = v;
        }
    }
    __syncthreads();

    float acc[OCPB][4];
    #pragma unroll
    for (int o = 0; o < OCPB; ++o)
        #pragma unroll
        for (int p = 0; p < 4; ++p) acc[o][p] = 0.f;

    for (int c = 0; c < CIN; ++c) {
        // prefetch next channel into registers (latency hidden by compute)
        float pfv[NPF];
        const bool have = (c + 1 < CIN);
        if (have) {
            const float* plane = plane_for(c + 1);
            #pragma unroll
            for (int k = 0; k < NPF; ++k) {
                int i = tid + k * 256;
                float v = 0.f;
                if (i < NTILE) {
                    int r = i / 66, cl = i % 66;
                    int gy = by0 + r - 1, gx = bx0 + cl - 1;
                    if ((unsigned)gy < HH && (unsigned)gx < WW) v = plane[gy * WW + gx];
                }
                pfv[k] = v;
            }
        }

        // compute from current buffer
        const float* sb = s_in + (size_t)(c & 1) * 18 * 68;
        float v[3][6];
        #pragma unroll
        for (int r = 0; r < 3; ++r) {
            const float* row = sb + (size_t)(ty + r) * 68 + txb;
            float4 a4 = *reinterpret_cast<const float4*>(row);
            float2 b2 = *reinterpret_cast<const float2*>(row + 4);
            v[r][0] = a4.x; v[r][1] = a4.y; v[r][2] = a4.z; v[r][3] = a4.w;
            v[r][4] = b2.x; v[r][5] = b2.y;
        }
        #pragma unroll
        for (int oc = 0; oc < OCPB; ++oc) {
            const float* wb = s_w + ((size_t)oc * CIN + c) * 12;
            float4 wa = *reinterpret_cast<const float4*>(wb);
            float4 wc = *reinterpret_cast<const float4*>(wb + 4);
            float4 wd = *reinterpret_cast<const float4*>(wb + 8);
            float wr[9] = {wa.x, wa.y, wa.z, wa.w, wc.x, wc.y, wc.z, wc.w, wd.x};
            #pragma unroll
            for (int ky = 0; ky < 3; ++ky)
                #pragma unroll
                for (int kx = 0; kx < 3; ++kx) {
                    float wv = wr[ky * 3 + kx];
                    #pragma unroll
                    for (int p = 0; p < 4; ++p)
                        acc[oc][p] = fmaf(v[ky][kx + p], wv, acc[oc][p]);
                }
        }

        // store prefetched channel into the other buffer
        if (have) {
            float* db = s_in + (size_t)((c + 1) & 1) * 18 * 68;
            #pragma unroll
            for (int k = 0; k < NPF; ++k) {
                int i = tid + k * 256;
                if (i < NTILE) {
                    int r = i / 66, cl = i % 66;
                    db[(size_t)r * 68 + cl] = pfv[k];
                }
            }
        }
        __syncthreads();
    }

    // epilogue (float4 stores; x base is 16B aligned)
    const int gy = by0 + ty;
    #pragma unroll
    for (int oc = 0; oc < OCPB; ++oc) {
        int oc_g = out_coff + ocb * OCPB + oc;
        size_t base = ((size_t)b * outC + oc_g) * HW + (size_t)gy * WW + bx0 + txb;
        float4 o4;
        float* ov = &o4.x;
        #pragma unroll
        for (int p = 0; p < 4; ++p) {
            float val = acc[oc][p];
            if (act) val = (val >= 0.f) ? val : 0.1f * val;
            ov[p] = val;
        }
        if (residual) {
            float4 r4 = *reinterpret_cast<const float4*>(&residual[base]);
            o4.x += r4.x; o4.y += r4.y; o4.z += r4.z; o4.w += r4.w;
        }
        *reinterpret_cast<float4*>(&out[base]) = o4;
    }
}

// ---------------- launch ----------------

static inline int conv_smem_bytes(int ocpb, int cin) {
    return (ocpb * cin * 12 + 2 * 18 * 68) * 4;
}

extern "C" void kernel_launch(void* const* d_in, const int* in_sizes, int n_in,
                              void* d_out, int out_size) {
    const float* feature0 = (const float*)d_in[0];
    const float* feature1 = (const float*)d_in[1];
    const float* biflow_p = (const float*)d_in[2];
    const float* fwd_t    = (const float*)d_in[3];
    const float* bwd_t    = (const float*)d_in[4];
    const float* Wt1 = (const float*)d_in[5];
    const float* Wt2 = (const float*)d_in[6];
    const float* Wt3 = (const float*)d_in[7];
    const float* Wt4 = (const float*)d_in[8];
    const float* Wt5 = (const float*)d_in[9];
    const float* Wt6 = (const float*)d_in[10];
    const float* Wt7 = (const float*)d_in[11];
    float* out = (float*)d_out;

    float *biflow, *accA, *accB, *warp0, *warp1, *vol, *h1, *h2;
    cudaGetSymbolAddress((void**)&biflow, g_biflow);
    cudaGetSymbolAddress((void**)&accA,   g_accA);
    cudaGetSymbolAddress((void**)&accB,   g_accB);
    cudaGetSymbolAddress((void**)&warp0,  g_warp0);
    cudaGetSymbolAddress((void**)&warp1,  g_warp1);
    cudaGetSymbolAddress((void**)&vol,    g_vol);
    cudaGetSymbolAddress((void**)&h1,     g_h1);
    cudaGetSymbolAddress((void**)&h2,     g_h2);

    // opt-in to >48KB dynamic smem (idempotent; host-side, not captured)
    static bool attr_done = false;
    if (!attr_done) {
        cudaFuncSetAttribute(conv3x3_v2<8>,  cudaFuncAttributeMaxDynamicSharedMemorySize,
                             conv_smem_bytes(8, 145));
        cudaFuncSetAttribute(conv3x3_v2<16>, cudaFuncAttributeMaxDynamicSharedMemorySize,
                             conv_smem_bytes(16, 64));
        cudaFuncSetAttribute(conv3x3_v2<2>,  cudaFuncAttributeMaxDynamicSharedMemorySize,
                             conv_smem_bytes(2, 16));
        attr_done = true;
    }

    // 1. upsample flow
    {
        int n = BB * 4 * HW;
        upsample_kernel<<<(n + 255) / 256, 256>>>(biflow_p, biflow);
    }
    // 2. zero accumulators
    {
        int n = BB * 33 * HW;
        zero_kernel<<<(n + 255) / 256, 256>>>(accA, n);
        zero_kernel<<<(n + 255) / 256, 256>>>(accB, n);
    }
    // 3. splats
    {
        int n = BB * HW;
        splat_kernel<<<(n + 255) / 256, 256>>>(feature0, biflow, 0, accA);
        splat_kernel<<<(n + 255) / 256, 256>>>(feature1, biflow, 2, accB);
    }
    // 4. normalize
    {
        int n = BB * 32 * HW;
        norm_kernel<<<(n + 255) / 256, 256>>>(accA, warp0);
        norm_kernel<<<(n + 255) / 256, 256>>>(accB, warp1);
    }
    // 5. correlation + leaky
    {
        dim3 g(HW / 256, BB);
        corr_kernel_v2<<<g, 256>>>(warp0, warp1, vol);
    }

    dim3 blk(16, 16);
    dim3 grd(WW / TW, HH / TH, 1);

    const int sm1   = conv_smem_bytes(8, 145);
    const int sm64  = conv_smem_bytes(16, 64);
    const int sm32  = conv_smem_bytes(16, 32);
    const int sm7   = conv_smem_bytes(2, 16);

    // branch forward: concat(warp0, fwd_t, vol) -> delta_f -> out[:, 0:2]
    grd.z = BB * 8;
    conv3x3_v2<8><<<grd, blk, sm1>>>(warp0, 32, fwd_t, 32, vol, 81, Wt1, h1, 64, 0, 145, 8, 0, nullptr);
    grd.z = BB * 4;
    conv3x3_v2<16><<<grd, blk, sm64>>>(h1, 64, nullptr, 0, nullptr, 0, Wt2, h2, 64, 0, 64, 4, 0, nullptr);
    conv3x3_v2<16><<<grd, blk, sm64>>>(h2, 64, nullptr, 0, nullptr, 0, Wt3, h1, 64, 0, 64, 4, 1, nullptr);
    grd.z = BB * 2;
    conv3x3_v2<16><<<grd, blk, sm64>>>(h1, 64, nullptr, 0, nullptr, 0, Wt4, h2, 32, 0, 64, 2, 0, nullptr);
    conv3x3_v2<16><<<grd, blk, sm32>>>(h2, 32, nullptr, 0, nullptr, 0, Wt5, h1, 32, 0, 32, 2, 0, nullptr);
    grd.z = BB * 1;
    conv3x3_v2<16><<<grd, blk, sm32>>>(h1, 32, nullptr, 0, nullptr, 0, Wt6, h2, 16, 0, 32, 1, 0, nullptr);
    conv3x3_v2<2><<<grd, blk, sm7>>>(h2, 16, nullptr, 0, nullptr, 0, Wt7, out, 4, 0, 16, 1, 1, biflow);

    // branch backward: concat(warp1, bwd_t, vol) -> delta_b -> out[:, 2:4]
    grd.z = BB * 8;
    conv3x3_v2<8><<<grd, blk, sm1>>>(warp1, 32, bwd_t, 32, vol, 81, Wt1, h1, 64, 0, 145, 8, 0, nullptr);
    grd.z = BB * 4;
    conv3x3_v2<16><<<grd, blk, sm64>>>(h1, 64, nullptr, 0, nullptr, 0, Wt2, h2, 64, 0, 64, 4, 0, nullptr);
    conv3x3_v2<16><<<grd, blk, sm64>>>(h2, 64, nullptr, 0, nullptr, 0, Wt3, h1, 64, 0, 64, 4, 1, nullptr);
    grd.z = BB * 2;
    conv3x3_v2<16><<<grd, blk, sm64>>>(h1, 64, nullptr, 0, nullptr, 0, Wt4, h2, 32, 0, 64, 2, 0, nullptr);
    conv3x3_v2<16><<<grd, blk, sm32>>>(h2, 32, nullptr, 0, nullptr, 0, Wt5, h1, 32, 0, 32, 2, 0, nullptr);
    grd.z = BB * 1;
    conv3x3_v2<16><<<grd, blk, sm32>>>(h1, 32, nullptr, 0, nullptr, 0, Wt6, h2, 16, 0, 32, 1, 0, nullptr);
    conv3x3_v2<2><<<grd, blk, sm7>>>(h2, 16, nullptr, 0, nullptr, 0, Wt7, out, 4, 2, 16, 1, 1, biflow);
}

// round 9
// speedup vs baseline: 2.0117x; 1.1054x over previous
#include <cuda_runtime.h>
#include <cstdint>
#include <cstdio>

#define BB 8
#define CC 32
#define HH 192
#define WW 320
#define HW (HH*WW)
#define UPH (HH/2)
#define UPW (WW/2)

// ---------------- scratch (static device globals; allocation-free) ----------------
__device__ float g_biflow[BB*4*HW];
__device__ float g_accA[BB*33*HW];
__device__ float g_accB[BB*33*HW];
__device__ float g_warp0[BB*32*HW];
__device__ float g_warp1[BB*32*HW];
__device__ float g_vol[BB*81*HW];
__device__ float g_h1[BB*64*HW];
__device__ float g_h2[BB*64*HW];

// ---------------- packed f32x2 helpers ----------------
__device__ __forceinline__ unsigned long long pack2(float x) {
    unsigned long long r;
    unsigned int u = __float_as_uint(x);
    asm("mov.b64 %0, {%1, %1};" : "=l"(r) : "r"(u));
    return r;
}
__device__ __forceinline__ void fma2(unsigned long long& d, unsigned long long a,
                                     unsigned long long b) {
    asm("fma.rn.f32x2 %0, %1, %2, %0;" : "+l"(d) : "l"(a), "l"(b));
}
__device__ __forceinline__ float2 unpack2(unsigned long long v) {
    unsigned int lo, hi;
    asm("mov.b64 {%0, %1}, %2;" : "=r"(lo), "=r"(hi) : "l"(v));
    return make_float2(__uint_as_float(lo), __uint_as_float(hi));
}

// ---------------- kernels ----------------

__global__ void zero_kernel(float* __restrict__ p, int n) {
    int i = blockIdx.x * blockDim.x + threadIdx.x;
    if (i < n) p[i] = 0.f;
}

__global__ void upsample_kernel(const float* __restrict__ src, float* __restrict__ dst) {
    int idx = blockIdx.x * blockDim.x + threadIdx.x;
    const int total = BB * 4 * HW;
    if (idx >= total) return;
    int x = idx % WW;
    int y = (idx / WW) % HH;
    int bc = idx / HW;
    float sx = 0.5f * x - 0.25f;
    float sy = 0.5f * y - 0.25f;
    sx = fminf(fmaxf(sx, 0.f), (float)(UPW - 1));
    sy = fminf(fmaxf(sy, 0.f), (float)(UPH - 1));
    int x0 = (int)floorf(sx);
    int y0 = (int)floorf(sy);
    float fx = sx - (float)x0;
    float fy = sy - (float)y0;
    int x1 = min(x0 + 1, UPW - 1);
    int y1 = min(y0 + 1, UPH - 1);
    const float* p = src + (size_t)bc * (UPH * UPW);
    float v00 = p[y0 * UPW + x0], v01 = p[y0 * UPW + x1];
    float v10 = p[y1 * UPW + x0], v11 = p[y1 * UPW + x1];
    float v = (1.f - fy) * ((1.f - fx) * v00 + fx * v01)
            +          fy * ((1.f - fx) * v10 + fx * v11);
    dst[idx] = 2.0f * v;
}

__global__ void splat_kernel(const float* __restrict__ feat,
                             const float* __restrict__ flow4, int fcoff,
                             float* __restrict__ acc) {
    int idx = blockIdx.x * blockDim.x + threadIdx.x;
    const int total = BB * HW;
    if (idx >= total) return;
    int x = idx % WW;
    int y = (idx / WW) % HH;
    int b = idx / HW;
    const float* fl = flow4 + ((size_t)b * 4 + fcoff) * HW + y * WW + x;
    float fx = (float)x + fl[0];
    float fy = (float)y + fl[(size_t)HW];
    float x0f = floorf(fx), y0f = floorf(fy);
    float wx1 = fx - x0f, wy1 = fy - y0f;
    float wx0 = 1.f - wx1, wy0 = 1.f - wy1;
    int ix0 = (int)x0f, iy0 = (int)y0f;
    int ixs[4] = {ix0, ix0 + 1, ix0, ix0 + 1};
    int iys[4] = {iy0, iy0, iy0 + 1, iy0 + 1};
    float ws[4] = {wx0 * wy0, wx1 * wy0, wx0 * wy1, wx1 * wy1};
    const float* fp = feat + (size_t)b * 32 * HW + y * WW + x;
    float* ap = acc + (size_t)b * 33 * HW;
    #pragma unroll
    for (int k = 0; k < 4; ++k) {
        int ix = ixs[k], iy = iys[k];
        if (ix < 0 || ix >= WW || iy < 0 || iy >= HH) continue;
        float w = ws[k];
        int off = iy * WW + ix;
        #pragma unroll
        for (int c = 0; c < 32; ++c)
            atomicAdd(ap + (size_t)c * HW + off, fp[(size_t)c * HW] * w);
        atomicAdd(ap + (size_t)32 * HW + off, w);
    }
}

__global__ void norm_kernel(const float* __restrict__ acc, float* __restrict__ warp) {
    int idx = blockIdx.x * blockDim.x + threadIdx.x;
    const int total = BB * 32 * HW;
    if (idx >= total) return;
    int p = idx % HW;
    int c = (idx / HW) % 32;
    int b = idx / (32 * HW);
    float n = acc[((size_t)b * 33 + 32) * HW + p];
    n = (n == 0.f) ? 1.f : n;
    warp[idx] = acc[((size_t)b * 33 + c) * HW + p] / n;
}

__global__ void __launch_bounds__(256)
corr_kernel_v2(const float* __restrict__ w0, const float* __restrict__ w1,
               float* __restrict__ vol) {
    int p = blockIdx.x * 256 + threadIdx.x;
    int b = blockIdx.y;
    int x = p % WW, y = p / WW;
    const float* a0 = w0 + (size_t)b * 32 * HW + p;
    float a[32];
    #pragma unroll
    for (int c = 0; c < 32; ++c) a[c] = a0[(size_t)c * HW];
    const float* bb = w1 + (size_t)b * 32 * HW;
    float* vp = vol + (size_t)b * 81 * HW + p;
    #pragma unroll 1
    for (int dy = -4; dy <= 4; ++dy) {
        int yy = y + dy;
        #pragma unroll 1
        for (int dx = -4; dx <= 4; ++dx) {
            int xx = x + dx;
            float s = 0.f;
            if (yy >= 0 && yy < HH && xx >= 0 && xx < WW) {
                const float* bp = bb + yy * WW + xx;
                #pragma unroll
                for (int c = 0; c < 32; ++c)
                    s = fmaf(a[c], bp[(size_t)c * HW], s);
                s *= (1.f / 32.f);
            }
            *vp = (s >= 0.f) ? s : 0.1f * s;
            vp += HW;
        }
    }
}

// ------------- Direct 3x3 conv v3: packed f32x2 over output-channel pairs -------------
// Tile 64(x) x 16(y) per 256-thread block; each thread: 4 x-pixels x OCPB out-channels.
// Weights in smem as (oc_even, oc_odd) float2 pairs -> LDS.64 gives a packed operand
// with no duplication. Input pixel value duplicated into both lanes once per channel.
// One __syncthreads per channel, register-prefetch double buffering.
#define TW 64
#define TH 16
#define NTILE (18*66)
#define NPF 5

template<int OCPB>
__global__ void __launch_bounds__(256)
conv3x3_v3(const float* __restrict__ in0, int c0,
           const float* __restrict__ in1, int c1,
           const float* __restrict__ in2, int c2,
           const float* __restrict__ wts,
           float* __restrict__ out, int outC, int out_coff,
           int CIN, int nOCB, int act,
           const float* __restrict__ residual) {
    constexpr int NOP = OCPB / 2;
    extern __shared__ float smem[];
    float* s_w  = smem;                               // [NOP][CIN][10] float2 (9 used)
    float* s_in = smem + (size_t)NOP * CIN * 20;      // [2][18][68]

    const int tid = threadIdx.y * 16 + threadIdx.x;
    const int bx0 = blockIdx.x * TW;
    const int by0 = blockIdx.y * TH;
    const int b   = blockIdx.z / nOCB;
    const int ocb = blockIdx.z % nOCB;
    const int ty  = threadIdx.y;
    const int txb = threadIdx.x * 4;

    auto plane_for = [&](int c) -> const float* {
        const float* src; int cc, sc;
        if (c < c0)           { src = in0; cc = c;           sc = c0; }
        else if (c < c0 + c1) { src = in1; cc = c - c0;      sc = c1; }
        else                  { src = in2; cc = c - c0 - c1; sc = c2; }
        return src + ((size_t)b * sc + cc) * HW;
    };

    // one-time weight preload: interleave oc pairs -> float2 lanes
    for (int i = tid; i < OCPB * CIN * 9; i += 256) {
        int oc = i / (CIN * 9);
        int r  = i % (CIN * 9);
        int ci = r / 9, k = r % 9;
        int op = oc >> 1, par = oc & 1;
        s_w[(((size_t)op * CIN + ci) * 10 + k) * 2 + par] =
            wts[((size_t)(ocb * OCPB + oc) * CIN + ci) * 9 + k];
    }
    // channel 0 tile into buffer 0
    {
        const float* plane = plane_for(0);
        for (int i = tid; i < NTILE; i += 256) {
            int r = i / 66, cl = i % 66;
            int gy = by0 + r - 1, gx = bx0 + cl - 1;
            float v = 0.f;
            if ((unsigned)gy < HH && (unsigned)gx < WW) v = plane[gy * WW + gx];
            s_in[(size_t)r * 68 + cl] = v;
        }
    }
    __syncthreads();

    unsigned long long acc2[NOP][4];
    #pragma unroll
    for (int o = 0; o < NOP; ++o)
        #pragma unroll
        for (int p = 0; p < 4; ++p) acc2[o][p] = 0ull;

    for (int c = 0; c < CIN; ++c) {
        float pfv[NPF];
        const bool have = (c + 1 < CIN);
        if (have) {
            const float* plane = plane_for(c + 1);
            #pragma unroll
            for (int k = 0; k < NPF; ++k) {
                int i = tid + k * 256;
                float v = 0.f;
                if (i < NTILE) {
                    int r = i / 66, cl = i % 66;
                    int gy = by0 + r - 1, gx = bx0 + cl - 1;
                    if ((unsigned)gy < HH && (unsigned)gx < WW) v = plane[gy * WW + gx];
                }
                pfv[k] = v;
            }
        }

        const float* sb = s_in + (size_t)(c & 1) * 18 * 68;
        unsigned long long vd[3][6];
        #pragma unroll
        for (int r = 0; r < 3; ++r) {
            const float* row = sb + (size_t)(ty + r) * 68 + txb;
            float4 a4 = *reinterpret_cast<const float4*>(row);
            float2 b2 = *reinterpret_cast<const float2*>(row + 4);
            vd[r][0] = pack2(a4.x); vd[r][1] = pack2(a4.y);
            vd[r][2] = pack2(a4.z); vd[r][3] = pack2(a4.w);
            vd[r][4] = pack2(b2.x); vd[r][5] = pack2(b2.y);
        }
        #pragma unroll
        for (int op = 0; op < NOP; ++op) {
            const unsigned long long* wp =
                reinterpret_cast<const unsigned long long*>(s_w) + ((size_t)op * CIN + c) * 10;
            ulonglong2 q0 = *reinterpret_cast<const ulonglong2*>(wp);
            ulonglong2 q1 = *reinterpret_cast<const ulonglong2*>(wp + 2);
            ulonglong2 q2 = *reinterpret_cast<const ulonglong2*>(wp + 4);
            ulonglong2 q3 = *reinterpret_cast<const ulonglong2*>(wp + 6);
            unsigned long long w2[9] = {q0.x, q0.y, q1.x, q1.y, q2.x, q2.y, q3.x, q3.y, wp[8]};
            #pragma unroll
            for (int ky = 0; ky < 3; ++ky)
                #pragma unroll
                for (int kx = 0; kx < 3; ++kx) {
                    #pragma unroll
                    for (int p = 0; p < 4; ++p)
                        fma2(acc2[op][p], vd[ky][kx + p], w2[ky * 3 + kx]);
                }
        }

        if (have) {
            float* db = s_in + (size_t)((c + 1) & 1) * 18 * 68;
            #pragma unroll
            for (int k = 0; k < NPF; ++k) {
                int i = tid + k * 256;
                if (i < NTILE) {
                    int r = i / 66, cl = i % 66;
                    db[(size_t)r * 68 + cl] = pfv[k];
                }
            }
        }
        __syncthreads();
    }

    // epilogue: unpack oc pairs, act/residual, float4 stores
    const int gy = by0 + ty;
    #pragma unroll
    for (int op = 0; op < NOP; ++op) {
        float o0[4], o1[4];
        #pragma unroll
        for (int p = 0; p < 4; ++p) {
            float2 u = unpack2(acc2[op][p]);
            o0[p] = u.x; o1[p] = u.y;
        }
        #pragma unroll
        for (int par = 0; par < 2; ++par) {
            float* ov = par ? o1 : o0;
            int oc_g = out_coff + ocb * OCPB + 2 * op + par;
            size_t base = ((size_t)b * outC + oc_g) * HW + (size_t)gy * WW + bx0 + txb;
            float4 o4;
            float vx[4];
            #pragma unroll
            for (int p = 0; p < 4; ++p) {
                float val = ov[p];
                if (act) val = (val >= 0.f) ? val : 0.1f * val;
                vx[p] = val;
            }
            o4.x = vx[0]; o4.y = vx[1]; o4.z = vx[2]; o4.w = vx[3];
            if (residual) {
                float4 r4 = *reinterpret_cast<const float4*>(&residual[base]);
                o4.x += r4.x; o4.y += r4.y; o4.z += r4.z; o4.w += r4.w;
            }
            *reinterpret_cast<float4*>(&out[base]) = o4;
        }
    }
}

// ---------------- launch ----------------

static inline int conv_smem_bytes(int ocpb, int cin) {
    return (ocpb / 2) * cin * 20 * 4 + 2 * 18 * 68 * 4;
}

extern "C" void kernel_launch(void* const* d_in, const int* in_sizes, int n_in,
                              void* d_out, int out_size) {
    const float* feature0 = (const float*)d_in[0];
    const float* feature1 = (const float*)d_in[1];
    const float* biflow_p = (const float*)d_in[2];
    const float* fwd_t    = (const float*)d_in[3];
    const float* bwd_t    = (const float*)d_in[4];
    const float* Wt1 = (const float*)d_in[5];
    const float* Wt2 = (const float*)d_in[6];
    const float* Wt3 = (const float*)d_in[7];
    const float* Wt4 = (const float*)d_in[8];
    const float* Wt5 = (const float*)d_in[9];
    const float* Wt6 = (const float*)d_in[10];
    const float* Wt7 = (const float*)d_in[11];
    float* out = (float*)d_out;

    float *biflow, *accA, *accB, *warp0, *warp1, *vol, *h1, *h2;
    cudaGetSymbolAddress((void**)&biflow, g_biflow);
    cudaGetSymbolAddress((void**)&accA,   g_accA);
    cudaGetSymbolAddress((void**)&accB,   g_accB);
    cudaGetSymbolAddress((void**)&warp0,  g_warp0);
    cudaGetSymbolAddress((void**)&warp1,  g_warp1);
    cudaGetSymbolAddress((void**)&vol,    g_vol);
    cudaGetSymbolAddress((void**)&h1,     g_h1);
    cudaGetSymbolAddress((void**)&h2,     g_h2);

    static bool attr_done = false;
    if (!attr_done) {
        cudaFuncSetAttribute(conv3x3_v3<8>,  cudaFuncAttributeMaxDynamicSharedMemorySize,
                             conv_smem_bytes(8, 145));
        cudaFuncSetAttribute(conv3x3_v3<16>, cudaFuncAttributeMaxDynamicSharedMemorySize,
                             conv_smem_bytes(16, 64));
        cudaFuncSetAttribute(conv3x3_v3<2>,  cudaFuncAttributeMaxDynamicSharedMemorySize,
                             conv_smem_bytes(2, 16));
        attr_done = true;
    }

    {
        int n = BB * 4 * HW;
        upsample_kernel<<<(n + 255) / 256, 256>>>(biflow_p, biflow);
    }
    {
        int n = BB * 33 * HW;
        zero_kernel<<<(n + 255) / 256, 256>>>(accA, n);
        zero_kernel<<<(n + 255) / 256, 256>>>(accB, n);
    }
    {
        int n = BB * HW;
        splat_kernel<<<(n + 255) / 256, 256>>>(feature0, biflow, 0, accA);
        splat_kernel<<<(n + 255) / 256, 256>>>(feature1, biflow, 2, accB);
    }
    {
        int n = BB * 32 * HW;
        norm_kernel<<<(n + 255) / 256, 256>>>(accA, warp0);
        norm_kernel<<<(n + 255) / 256, 256>>>(accB, warp1);
    }
    {
        dim3 g(HW / 256, BB);
        corr_kernel_v2<<<g, 256>>>(warp0, warp1, vol);
    }

    dim3 blk(16, 16);
    dim3 grd(WW / TW, HH / TH, 1);

    const int sm1   = conv_smem_bytes(8, 145);
    const int sm64  = conv_smem_bytes(16, 64);
    const int sm32  = conv_smem_bytes(16, 32);
    const int sm7   = conv_smem_bytes(2, 16);

    // forward branch
    grd.z = BB * 8;
    conv3x3_v3<8><<<grd, blk, sm1>>>(warp0, 32, fwd_t, 32, vol, 81, Wt1, h1, 64, 0, 145, 8, 0, nullptr);
    grd.z = BB * 4;
    conv3x3_v3<16><<<grd, blk, sm64>>>(h1, 64, nullptr, 0, nullptr, 0, Wt2, h2, 64, 0, 64, 4, 0, nullptr);
    conv3x3_v3<16><<<grd, blk, sm64>>>(h2, 64, nullptr, 0, nullptr, 0, Wt3, h1, 64, 0, 64, 4, 1, nullptr);
    grd.z = BB * 2;
    conv3x3_v3<16><<<grd, blk, sm64>>>(h1, 64, nullptr, 0, nullptr, 0, Wt4, h2, 32, 0, 64, 2, 0, nullptr);
    conv3x3_v3<16><<<grd, blk, sm32>>>(h2, 32, nullptr, 0, nullptr, 0, Wt5, h1, 32, 0, 32, 2, 0, nullptr);
    grd.z = BB * 1;
    conv3x3_v3<16><<<grd, blk, sm32>>>(h1, 32, nullptr, 0, nullptr, 0, Wt6, h2, 16, 0, 32, 1, 0, nullptr);
    conv3x3_v3<2><<<grd, blk, sm7>>>(h2, 16, nullptr, 0, nullptr, 0, Wt7, out, 4, 0, 16, 1, 1, biflow);

    // backward branch
    grd.z = BB * 8;
    conv3x3_v3<8><<<grd, blk, sm1>>>(warp1, 32, bwd_t, 32, vol, 81, Wt1, h1, 64, 0, 145, 8, 0, nullptr);
    grd.z = BB * 4;
    conv3x3_v3<16><<<grd, blk, sm64>>>(h1, 64, nullptr, 0, nullptr, 0, Wt2, h2, 64, 0, 64, 4, 0, nullptr);
    conv3x3_v3<16><<<grd, blk, sm64>>>(h2, 64, nullptr, 0, nullptr, 0, Wt3, h1, 64, 0, 64, 4, 1, nullptr);
    grd.z = BB * 2;
    conv3x3_v3<16><<<grd, blk, sm64>>>(h1, 64, nullptr, 0, nullptr, 0, Wt4, h2, 32, 0, 64, 2, 0, nullptr);
    conv3x3_v3<16><<<grd, blk, sm32>>>(h2, 32, nullptr, 0, nullptr, 0, Wt5, h1, 32, 0, 32, 2, 0, nullptr);
    grd.z = BB * 1;
    conv3x3_v3<16><<<grd, blk, sm32>>>(h1, 32, nullptr, 0, nullptr, 0, Wt6, h2, 16, 0, 32, 1, 0, nullptr);
    conv3x3_v3<2><<<grd, blk, sm7>>>(h2, 16, nullptr, 0, nullptr, 0, Wt7, out, 4, 2, 16, 1, 1, biflow);
}

// round 10
// speedup vs baseline: 2.0133x; 1.0008x over previous
#include <cuda_runtime.h>
#include <cstdint>
#include <cstdio>

#define BB 8
#define CC 32
#define HH 192
#define WW 320
#define HW (HH*WW)
#define UPH (HH/2)
#define UPW (WW/2)

// ---------------- scratch (static device globals; allocation-free) ----------------
__device__ float g_biflow[BB*4*HW];
__device__ float g_accA[BB*33*HW];
__device__ float g_accB[BB*33*HW];
__device__ float g_warp0[BB*32*HW];
__device__ float g_warp1[BB*32*HW];
__device__ float g_vol[BB*81*HW];
__device__ float g_h1[BB*64*HW];
__device__ float g_h2[BB*64*HW];

// ---------------- packed f32x2 helpers ----------------
__device__ __forceinline__ unsigned long long pack2(float x) {
    unsigned long long r;
    unsigned int u = __float_as_uint(x);
    asm("mov.b64 %0, {%1, %1};" : "=l"(r) : "r"(u));
    return r;
}
__device__ __forceinline__ void fma2(unsigned long long& d, unsigned long long a,
                                     unsigned long long b) {
    asm("fma.rn.f32x2 %0, %1, %2, %0;" : "+l"(d) : "l"(a), "l"(b));
}
__device__ __forceinline__ float2 unpack2(unsigned long long v) {
    unsigned int lo, hi;
    asm("mov.b64 {%0, %1}, %2;" : "=r"(lo), "=r"(hi) : "l"(v));
    return make_float2(__uint_as_float(lo), __uint_as_float(hi));
}

// ---------------- kernels ----------------

__global__ void zero_kernel(float* __restrict__ p, int n) {
    int i = blockIdx.x * blockDim.x + threadIdx.x;
    if (i < n) p[i] = 0.f;
}

__global__ void upsample_kernel(const float* __restrict__ src, float* __restrict__ dst) {
    int idx = blockIdx.x * blockDim.x + threadIdx.x;
    const int total = BB * 4 * HW;
    if (idx >= total) return;
    int x = idx % WW;
    int y = (idx / WW) % HH;
    int bc = idx / HW;
    float sx = 0.5f * x - 0.25f;
    float sy = 0.5f * y - 0.25f;
    sx = fminf(fmaxf(sx, 0.f), (float)(UPW - 1));
    sy = fminf(fmaxf(sy, 0.f), (float)(UPH - 1));
    int x0 = (int)floorf(sx);
    int y0 = (int)floorf(sy);
    float fx = sx - (float)x0;
    float fy = sy - (float)y0;
    int x1 = min(x0 + 1, UPW - 1);
    int y1 = min(y0 + 1, UPH - 1);
    const float* p = src + (size_t)bc * (UPH * UPW);
    float v00 = p[y0 * UPW + x0], v01 = p[y0 * UPW + x1];
    float v10 = p[y1 * UPW + x0], v11 = p[y1 * UPW + x1];
    float v = (1.f - fy) * ((1.f - fx) * v00 + fx * v01)
            +          fy * ((1.f - fx) * v10 + fx * v11);
    dst[idx] = 2.0f * v;
}

__global__ void splat_kernel(const float* __restrict__ feat,
                             const float* __restrict__ flow4, int fcoff,
                             float* __restrict__ acc) {
    int idx = blockIdx.x * blockDim.x + threadIdx.x;
    const int total = BB * HW;
    if (idx >= total) return;
    int x = idx % WW;
    int y = (idx / WW) % HH;
    int b = idx / HW;
    const float* fl = flow4 + ((size_t)b * 4 + fcoff) * HW + y * WW + x;
    float fx = (float)x + fl[0];
    float fy = (float)y + fl[(size_t)HW];
    float x0f = floorf(fx), y0f = floorf(fy);
    float wx1 = fx - x0f, wy1 = fy - y0f;
    float wx0 = 1.f - wx1, wy0 = 1.f - wy1;
    int ix0 = (int)x0f, iy0 = (int)y0f;
    int ixs[4] = {ix0, ix0 + 1, ix0, ix0 + 1};
    int iys[4] = {iy0, iy0, iy0 + 1, iy0 + 1};
    float ws[4] = {wx0 * wy0, wx1 * wy0, wx0 * wy1, wx1 * wy1};
    const float* fp = feat + (size_t)b * 32 * HW + y * WW + x;
    float* ap = acc + (size_t)b * 33 * HW;
    #pragma unroll
    for (int k = 0; k < 4; ++k) {
        int ix = ixs[k], iy = iys[k];
        if (ix < 0 || ix >= WW || iy < 0 || iy >= HH) continue;
        float w = ws[k];
        int off = iy * WW + ix;
        #pragma unroll
        for (int c = 0; c < 32; ++c)
            atomicAdd(ap + (size_t)c * HW + off, fp[(size_t)c * HW] * w);
        atomicAdd(ap + (size_t)32 * HW + off, w);
    }
}

__global__ void norm_kernel(const float* __restrict__ acc, float* __restrict__ warp) {
    int idx = blockIdx.x * blockDim.x + threadIdx.x;
    const int total = BB * 32 * HW;
    if (idx >= total) return;
    int p = idx % HW;
    int c = (idx / HW) % 32;
    int b = idx / (32 * HW);
    float n = acc[((size_t)b * 33 + 32) * HW + p];
    n = (n == 0.f) ? 1.f : n;
    warp[idx] = acc[((size_t)b * 33 + c) * HW + p] / n;
}

__global__ void __launch_bounds__(256)
corr_kernel_v2(const float* __restrict__ w0, const float* __restrict__ w1,
               float* __restrict__ vol) {
    int p = blockIdx.x * 256 + threadIdx.x;
    int b = blockIdx.y;
    int x = p % WW, y = p / WW;
    const float* a0 = w0 + (size_t)b * 32 * HW + p;
    float a[32];
    #pragma unroll
    for (int c = 0; c < 32; ++c) a[c] = a0[(size_t)c * HW];
    const float* bb = w1 + (size_t)b * 32 * HW;
    float* vp = vol + (size_t)b * 81 * HW + p;
    #pragma unroll 1
    for (int dy = -4; dy <= 4; ++dy) {
        int yy = y + dy;
        #pragma unroll 1
        for (int dx = -4; dx <= 4; ++dx) {
            int xx = x + dx;
            float s = 0.f;
            if (yy >= 0 && yy < HH && xx >= 0 && xx < WW) {
                const float* bp = bb + yy * WW + xx;
                #pragma unroll
                for (int c = 0; c < 32; ++c)
                    s = fmaf(a[c], bp[(size_t)c * HW], s);
                s *= (1.f / 32.f);
            }
            *vp = (s >= 0.f) ? s : 0.1f * s;
            vp += HW;
        }
    }
}

// ------------- Direct 3x3 conv v3: packed f32x2 over output-channel pairs -------------
// Tile 64(x) x 16(y) per 256-thread block; each thread: 4 x-pixels x OCPB out-channels.
// Weights in smem as (oc_even, oc_odd) float2 pairs -> LDS.64 gives a packed operand
// with no duplication. Input pixel value duplicated into both lanes once per channel.
// One __syncthreads per channel, register-prefetch double buffering.
#define TW 64
#define TH 16
#define NTILE (18*66)
#define NPF 5

template<int OCPB>
__global__ void __launch_bounds__(256)
conv3x3_v3(const float* __restrict__ in0, int c0,
           const float* __restrict__ in1, int c1,
           const float* __restrict__ in2, int c2,
           const float* __restrict__ wts,
           float* __restrict__ out, int outC, int out_coff,
           int CIN, int nOCB, int act,
           const float* __restrict__ residual) {
    constexpr int NOP = OCPB / 2;
    extern __shared__ float smem[];
    float* s_w  = smem;                               // [NOP][CIN][10] float2 (9 used)
    float* s_in = smem + (size_t)NOP * CIN * 20;      // [2][18][68]

    const int tid = threadIdx.y * 16 + threadIdx.x;
    const int bx0 = blockIdx.x * TW;
    const int by0 = blockIdx.y * TH;
    const int b   = blockIdx.z / nOCB;
    const int ocb = blockIdx.z % nOCB;
    const int ty  = threadIdx.y;
    const int txb = threadIdx.x * 4;

    auto plane_for = [&](int c) -> const float* {
        const float* src; int cc, sc;
        if (c < c0)           { src = in0; cc = c;           sc = c0; }
        else if (c < c0 + c1) { src = in1; cc = c - c0;      sc = c1; }
        else                  { src = in2; cc = c - c0 - c1; sc = c2; }
        return src + ((size_t)b * sc + cc) * HW;
    };

    // one-time weight preload: interleave oc pairs -> float2 lanes
    for (int i = tid; i < OCPB * CIN * 9; i += 256) {
        int oc = i / (CIN * 9);
        int r  = i % (CIN * 9);
        int ci = r / 9, k = r % 9;
        int op = oc >> 1, par = oc & 1;
        s_w[(((size_t)op * CIN + ci) * 10 + k) * 2 + par] =
            wts[((size_t)(ocb * OCPB + oc) * CIN + ci) * 9 + k];
    }
    // channel 0 tile into buffer 0
    {
        const float* plane = plane_for(0);
        for (int i = tid; i < NTILE; i += 256) {
            int r = i / 66, cl = i % 66;
            int gy = by0 + r - 1, gx = bx0 + cl - 1;
            float v = 0.f;
            if ((unsigned)gy < HH && (unsigned)gx < WW) v = plane[gy * WW + gx];
            s_in[(size_t)r * 68 + cl] = v;
        }
    }
    __syncthreads();

    unsigned long long acc2[NOP][4];
    #pragma unroll
    for (int o = 0; o < NOP; ++o)
        #pragma unroll
        for (int p = 0; p < 4; ++p) acc2[o][p] = 0ull;

    for (int c = 0; c < CIN; ++c) {
        float pfv[NPF];
        const bool have = (c + 1 < CIN);
        if (have) {
            const float* plane = plane_for(c + 1);
            #pragma unroll
            for (int k = 0; k < NPF; ++k) {
                int i = tid + k * 256;
                float v = 0.f;
                if (i < NTILE) {
                    int r = i / 66, cl = i % 66;
                    int gy = by0 + r - 1, gx = bx0 + cl - 1;
                    if ((unsigned)gy < HH && (unsigned)gx < WW) v = plane[gy * WW + gx];
                }
                pfv[k] = v;
            }
        }

        const float* sb = s_in + (size_t)(c & 1) * 18 * 68;
        unsigned long long vd[3][6];
        #pragma unroll
        for (int r = 0; r < 3; ++r) {
            const float* row = sb + (size_t)(ty + r) * 68 + txb;
            float4 a4 = *reinterpret_cast<const float4*>(row);
            float2 b2 = *reinterpret_cast<const float2*>(row + 4);
            vd[r][0] = pack2(a4.x); vd[r][1] = pack2(a4.y);
            vd[r][2] = pack2(a4.z); vd[r][3] = pack2(a4.w);
            vd[r][4] = pack2(b2.x); vd[r][5] = pack2(b2.y);
        }
        #pragma unroll
        for (int op = 0; op < NOP; ++op) {
            const unsigned long long* wp =
                reinterpret_cast<const unsigned long long*>(s_w) + ((size_t)op * CIN + c) * 10;
            ulonglong2 q0 = *reinterpret_cast<const ulonglong2*>(wp);
            ulonglong2 q1 = *reinterpret_cast<const ulonglong2*>(wp + 2);
            ulonglong2 q2 = *reinterpret_cast<const ulonglong2*>(wp + 4);
            ulonglong2 q3 = *reinterpret_cast<const ulonglong2*>(wp + 6);
            unsigned long long w2[9] = {q0.x, q0.y, q1.x, q1.y, q2.x, q2.y, q3.x, q3.y, wp[8]};
            #pragma unroll
            for (int ky = 0; ky < 3; ++ky)
                #pragma unroll
                for (int kx = 0; kx < 3; ++kx) {
                    #pragma unroll
                    for (int p = 0; p < 4; ++p)
                        fma2(acc2[op][p], vd[ky][kx + p], w2[ky * 3 + kx]);
                }
        }

        if (have) {
            float* db = s_in + (size_t)((c + 1) & 1) * 18 * 68;
            #pragma unroll
            for (int k = 0; k < NPF; ++k) {
                int i = tid + k * 256;
                if (i < NTILE) {
                    int r = i / 66, cl = i % 66;
                    db[(size_t)r * 68 + cl] = pfv[k];
                }
            }
        }
        __syncthreads();
    }

    // epilogue: unpack oc pairs, act/residual, float4 stores
    const int gy = by0 + ty;
    #pragma unroll
    for (int op = 0; op < NOP; ++op) {
        float o0[4], o1[4];
        #pragma unroll
        for (int p = 0; p < 4; ++p) {
            float2 u = unpack2(acc2[op][p]);
            o0[p] = u.x; o1[p] = u.y;
        }
        #pragma unroll
        for (int par = 0; par < 2; ++par) {
            float* ov = par ? o1 : o0;
            int oc_g = out_coff + ocb * OCPB + 2 * op + par;
            size_t base = ((size_t)b * outC + oc_g) * HW + (size_t)gy * WW + bx0 + txb;
            float4 o4;
            float vx[4];
            #pragma unroll
            for (int p = 0; p < 4; ++p) {
                float val = ov[p];
                if (act) val = (val >= 0.f) ? val : 0.1f * val;
                vx[p] = val;
            }
            o4.x = vx[0]; o4.y = vx[1]; o4.z = vx[2]; o4.w = vx[3];
            if (residual) {
                float4 r4 = *reinterpret_cast<const float4*>(&residual[base]);
                o4.x += r4.x; o4.y += r4.y; o4.z += r4.z; o4.w += r4.w;
            }
            *reinterpret_cast<float4*>(&out[base]) = o4;
        }
    }
}

// ---------------- launch ----------------

static inline int conv_smem_bytes(int ocpb, int cin) {
    return (ocpb / 2) * cin * 20 * 4 + 2 * 18 * 68 * 4;
}

extern "C" void kernel_launch(void* const* d_in, const int* in_sizes, int n_in,
                              void* d_out, int out_size) {
    const float* feature0 = (const float*)d_in[0];
    const float* feature1 = (const float*)d_in[1];
    const float* biflow_p = (const float*)d_in[2];
    const float* fwd_t    = (const float*)d_in[3];
    const float* bwd_t    = (const float*)d_in[4];
    const float* Wt1 = (const float*)d_in[5];
    const float* Wt2 = (const float*)d_in[6];
    const float* Wt3 = (const float*)d_in[7];
    const float* Wt4 = (const float*)d_in[8];
    const float* Wt5 = (const float*)d_in[9];
    const float* Wt6 = (const float*)d_in[10];
    const float* Wt7 = (const float*)d_in[11];
    float* out = (float*)d_out;

    float *biflow, *accA, *accB, *warp0, *warp1, *vol, *h1, *h2;
    cudaGetSymbolAddress((void**)&biflow, g_biflow);
    cudaGetSymbolAddress((void**)&accA,   g_accA);
    cudaGetSymbolAddress((void**)&accB,   g_accB);
    cudaGetSymbolAddress((void**)&warp0,  g_warp0);
    cudaGetSymbolAddress((void**)&warp1,  g_warp1);
    cudaGetSymbolAddress((void**)&vol,    g_vol);
    cudaGetSymbolAddress((void**)&h1,     g_h1);
    cudaGetSymbolAddress((void**)&h2,     g_h2);

    static bool attr_done = false;
    if (!attr_done) {
        cudaFuncSetAttribute(conv3x3_v3<8>,  cudaFuncAttributeMaxDynamicSharedMemorySize,
                             conv_smem_bytes(8, 145));
        cudaFuncSetAttribute(conv3x3_v3<16>, cudaFuncAttributeMaxDynamicSharedMemorySize,
                             conv_smem_bytes(16, 64));
        cudaFuncSetAttribute(conv3x3_v3<2>,  cudaFuncAttributeMaxDynamicSharedMemorySize,
                             conv_smem_bytes(2, 16));
        attr_done = true;
    }

    {
        int n = BB * 4 * HW;
        upsample_kernel<<<(n + 255) / 256, 256>>>(biflow_p, biflow);
    }
    {
        int n = BB * 33 * HW;
        zero_kernel<<<(n + 255) / 256, 256>>>(accA, n);
        zero_kernel<<<(n + 255) / 256, 256>>>(accB, n);
    }
    {
        int n = BB * HW;
        splat_kernel<<<(n + 255) / 256, 256>>>(feature0, biflow, 0, accA);
        splat_kernel<<<(n + 255) / 256, 256>>>(feature1, biflow, 2, accB);
    }
    {
        int n = BB * 32 * HW;
        norm_kernel<<<(n + 255) / 256, 256>>>(accA, warp0);
        norm_kernel<<<(n + 255) / 256, 256>>>(accB, warp1);
    }
    {
        dim3 g(HW / 256, BB);
        corr_kernel_v2<<<g, 256>>>(warp0, warp1, vol);
    }

    dim3 blk(16, 16);
    dim3 grd(WW / TW, HH / TH, 1);

    const int sm1   = conv_smem_bytes(8, 145);
    const int sm64  = conv_smem_bytes(16, 64);
    const int sm32  = conv_smem_bytes(16, 32);
    const int sm7   = conv_smem_bytes(2, 16);

    // forward branch
    grd.z = BB * 8;
    conv3x3_v3<8><<<grd, blk, sm1>>>(warp0, 32, fwd_t, 32, vol, 81, Wt1, h1, 64, 0, 145, 8, 0, nullptr);
    grd.z = BB * 4;
    conv3x3_v3<16><<<grd, blk, sm64>>>(h1, 64, nullptr, 0, nullptr, 0, Wt2, h2, 64, 0, 64, 4, 0, nullptr);
    conv3x3_v3<16><<<grd, blk, sm64>>>(h2, 64, nullptr, 0, nullptr, 0, Wt3, h1, 64, 0, 64, 4, 1, nullptr);
    grd.z = BB * 2;
    conv3x3_v3<16><<<grd, blk, sm64>>>(h1, 64, nullptr, 0, nullptr, 0, Wt4, h2, 32, 0, 64, 2, 0, nullptr);
    conv3x3_v3<16><<<grd, blk, sm32>>>(h2, 32, nullptr, 0, nullptr, 0, Wt5, h1, 32, 0, 32, 2, 0, nullptr);
    grd.z = BB * 1;
    conv3x3_v3<16><<<grd, blk, sm32>>>(h1, 32, nullptr, 0, nullptr, 0, Wt6, h2, 16, 0, 32, 1, 0, nullptr);
    conv3x3_v3<2><<<grd, blk, sm7>>>(h2, 16, nullptr, 0, nullptr, 0, Wt7, out, 4, 0, 16, 1, 1, biflow);

    // backward branch
    grd.z = BB * 8;
    conv3x3_v3<8><<<grd, blk, sm1>>>(warp1, 32, bwd_t, 32, vol, 81, Wt1, h1, 64, 0, 145, 8, 0, nullptr);
    grd.z = BB * 4;
    conv3x3_v3<16><<<grd, blk, sm64>>>(h1, 64, nullptr, 0, nullptr, 0, Wt2, h2, 64, 0, 64, 4, 0, nullptr);
    conv3x3_v3<16><<<grd, blk, sm64>>>(h2, 64, nullptr, 0, nullptr, 0, Wt3, h1, 64, 0, 64, 4, 1, nullptr);
    grd.z = BB * 2;
    conv3x3_v3<16><<<grd, blk, sm64>>>(h1, 64, nullptr, 0, nullptr, 0, Wt4, h2, 32, 0, 64, 2, 0, nullptr);
    conv3x3_v3<16><<<grd, blk, sm32>>>(h2, 32, nullptr, 0, nullptr, 0, Wt5, h1, 32, 0, 32, 2, 0, nullptr);
    grd.z = BB * 1;
    conv3x3_v3<16><<<grd, blk, sm32>>>(h1, 32, nullptr, 0, nullptr, 0, Wt6, h2, 16, 0, 32, 1, 0, nullptr);
    conv3x3_v3<2><<<grd, blk, sm7>>>(h2, 16, nullptr, 0, nullptr, 0, Wt7, out, 4, 2, 16, 1, 1, biflow);
}

// round 15
// speedup vs baseline: 2.0344x; 1.0105x over previous
#include <cuda_runtime.h>
#include <cuda_bf16.h>
#include <cstdint>

#define BB 8
#define HH 192
#define WW 320
#define HW (HH*WW)
#define UPH (HH/2)
#define UPW (WW/2)

__device__ float    g_biflow[BB*4*HW];
__device__ float    g_accA[BB*33*HW];
__device__ float    g_accB[BB*33*HW];
__device__ float    g_warp0[BB*32*HW];
__device__ float    g_warp1[BB*32*HW];
__device__ unsigned g_w0p[BB*32*HW];
__device__ unsigned g_w1p[BB*32*HW];
__device__ unsigned g_ftp[BB*32*HW];
__device__ unsigned g_btp[BB*32*HW];
__device__ unsigned g_volp[BB*81*HW];
__device__ unsigned g_h1p[BB*64*HW];
__device__ unsigned g_h2p[BB*64*HW];
__device__ float    g_h6f[BB*16*HW];
__device__ __align__(16) __nv_bfloat16 g_wprep[460800];

__device__ __forceinline__ unsigned pack_hl(float v) {
    __nv_bfloat16 h = __float2bfloat16(v);
    __nv_bfloat16 l = __float2bfloat16(v - __bfloat162float(h));
    return (unsigned)__bfloat16_as_ushort(h) | ((unsigned)__bfloat16_as_ushort(l) << 16);
}

__device__ __forceinline__ uint32_t smem_u32(const void* p) {
    uint32_t a;
    asm("{ .reg .u64 t; cvta.to.shared.u64 t, %1; cvt.u32.u64 %0, t; }" : "=r"(a) : "l"(p));
    return a;
}

__device__ __forceinline__ void ldmatrix_x4(unsigned* r, uint32_t addr) {
    asm volatile("ldmatrix.sync.aligned.m8n8.x4.shared.b16 {%0,%1,%2,%3}, [%4];"
        : "=r"(r[0]), "=r"(r[1]), "=r"(r[2]), "=r"(r[3]) : "r"(addr));
}

__device__ __forceinline__ void mma16816(float* d, const unsigned* a, unsigned b0, unsigned b1) {
    asm volatile(
        "mma.sync.aligned.m16n8k16.row.col.f32.bf16.bf16.f32 "
        "{%0,%1,%2,%3}, {%4,%5,%6,%7}, {%8,%9}, {%0,%1,%2,%3};"
        : "+f"(d[0]), "+f"(d[1]), "+f"(d[2]), "+f"(d[3])
        : "r"(a[0]), "r"(a[1]), "r"(a[2]), "r"(a[3]), "r"(b0), "r"(b1));
}

// ---------- front-end ----------
__global__ void zero_kernel(float* p, int n) {
    int i = blockIdx.x * 256 + threadIdx.x;
    if (i < n) p[i] = 0.f;
}
__global__ void pack_kernel(const float* __restrict__ s, unsigned* __restrict__ d, int n) {
    int i = blockIdx.x * 256 + threadIdx.x;
    if (i < n) d[i] = pack_hl(s[i]);
}
__global__ void upsample_kernel(const float* __restrict__ src, float* __restrict__ dst) {
    int idx = blockIdx.x * 256 + threadIdx.x;
    if (idx >= BB * 4 * HW) return;
    int x = idx % WW, y = (idx / WW) % HH, bc = idx / HW;
    float sx = fminf(fmaxf(0.5f * x - 0.25f, 0.f), (float)(UPW - 1));
    float sy = fminf(fmaxf(0.5f * y - 0.25f, 0.f), (float)(UPH - 1));
    int x0 = (int)floorf(sx), y0 = (int)floorf(sy);
    float fx = sx - x0, fy = sy - y0;
    int x1 = min(x0 + 1, UPW - 1), y1 = min(y0 + 1, UPH - 1);
    const float* p = src + (size_t)bc * (UPH * UPW);
    float v = (1.f - fy) * ((1.f - fx) * p[y0 * UPW + x0] + fx * p[y0 * UPW + x1])
            +          fy * ((1.f - fx) * p[y1 * UPW + x0] + fx * p[y1 * UPW + x1]);
    dst[idx] = 2.0f * v;
}
__global__ void splat_kernel(const float* __restrict__ feat, const float* __restrict__ flow4,
                             int fcoff, float* __restrict__ acc) {
    int idx = blockIdx.x * 256 + threadIdx.x;
    if (idx >= BB * HW) return;
    int x = idx % WW, y = (idx / WW) % HH, b = idx / HW;
    const float* fl = flow4 + ((size_t)b * 4 + fcoff) * HW + y * WW + x;
    float fx = x + fl[0], fy = y + fl[(size_t)HW];
    float x0f = floorf(fx), y0f = floorf(fy);
    float wx1 = fx - x0f, wy1 = fy - y0f, wx0 = 1.f - wx1, wy0 = 1.f - wy1;
    int ix0 = (int)x0f, iy0 = (int)y0f;
    int ixs[4] = {ix0, ix0 + 1, ix0, ix0 + 1};
    int iys[4] = {iy0, iy0, iy0 + 1, iy0 + 1};
    float ws[4] = {wx0 * wy0, wx1 * wy0, wx0 * wy1, wx1 * wy1};
    const float* fp = feat + (size_t)b * 32 * HW + y * WW + x;
    float* ap = acc + (size_t)b * 33 * HW;
    #pragma unroll
    for (int k = 0; k < 4; ++k) {
        int ix = ixs[k], iy = iys[k];
        if (ix < 0 || ix >= WW || iy < 0 || iy >= HH) continue;
        int off = iy * WW + ix;
        #pragma unroll
        for (int c = 0; c < 32; ++c)
            atomicAdd(ap + (size_t)c * HW + off, fp[(size_t)c * HW] * ws[k]);
        atomicAdd(ap + (size_t)32 * HW + off, ws[k]);
    }
}
__global__ void norm_kernel(const float* __restrict__ acc, float* __restrict__ warp,
                            unsigned* __restrict__ warpP) {
    int idx = blockIdx.x * 256 + threadIdx.x;
    if (idx >= BB * 32 * HW) return;
    int p = idx % HW, b = idx / (32 * HW), c = (idx / HW) % 32;
    float n = acc[((size_t)b * 33 + 32) * HW + p];
    n = (n == 0.f) ? 1.f : n;
    float v = acc[((size_t)b * 33 + c) * HW + p] / n;
    warp[idx] = v;
    warpP[idx] = pack_hl(v);
}
__global__ void __launch_bounds__(256)
corr_kernel(const float* __restrict__ w0, const float* __restrict__ w1,
            unsigned* __restrict__ volP) {
    int p = blockIdx.x * 256 + threadIdx.x;
    int b = blockIdx.y;
    int x = p % WW, y = p / WW;
    const float* a0 = w0 + (size_t)b * 32 * HW + p;
    float a[32];
    #pragma unroll
    for (int c = 0; c < 32; ++c) a[c] = a0[(size_t)c * HW];
    const float* bb = w1 + (size_t)b * 32 * HW;
    unsigned* vp = volP + (size_t)b * 81 * HW + p;
    #pragma unroll 1
    for (int dy = -4; dy <= 4; ++dy) {
        int yy = y + dy;
        #pragma unroll 1
        for (int dx = -4; dx <= 4; ++dx) {
            int xx = x + dx;
            float s = 0.f;
            if ((unsigned)yy < HH && (unsigned)xx < WW) {
                const float* bp = bb + yy * WW + xx;
                #pragma unroll
                for (int c = 0; c < 32; ++c) s = fmaf(a[c], bp[(size_t)c * HW], s);
                s *= (1.f / 32.f);
            }
            s = (s >= 0.f) ? s : 0.1f * s;
            *vp = pack_hl(s);
            vp += HW;
        }
    }
}

// weight prep: fp32 [oc][cin][9] -> bf16 [ch][tap][hf][oc][16k] (plain layout)
__global__ void prep_w_kernel(const float* __restrict__ Wt, int OC, int CIN, int nch,
                              __nv_bfloat16* __restrict__ dst) {
    int n = nch * 9 * 2 * OC * 16;
    int e = blockIdx.x * 256 + threadIdx.x;
    if (e >= n) return;
    int k = e & 15, r = e >> 4;
    int oc = r % OC; r /= OC;
    int hf = r & 1; r >>= 1;
    int tap = r % 9, ch = r / 9;
    int cin = ch * 16 + k;
    float w = (cin < CIN) ? Wt[((size_t)oc * CIN + cin) * 9 + tap] : 0.f;
    __nv_bfloat16 h = __float2bfloat16(w);
    dst[e] = hf ? __float2bfloat16(w - __bfloat162float(h)) : h;
}

// ---------- HMMA conv: 128-px tile (2x64), ldmatrix A, plain-indexed B ----------
template<int OC, int OUTF, int ACT>
__global__ void __launch_bounds__(256)
convM(const unsigned* __restrict__ s0, int c0, const unsigned* __restrict__ s1, int c1,
      const unsigned* __restrict__ s2, int c2, int cintot, int nch,
      const __nv_bfloat16* __restrict__ wprep,
      unsigned* __restrict__ outP, float* __restrict__ outF) {
    constexpr int NT = OC / 8;
    extern __shared__ unsigned smem[];
    unsigned* sA = smem;                 // 2*264*12 = 6336 u32
    unsigned* sW = smem + 6336;          // 9*2*OC*8 u32

    const int tid = threadIdx.x, lane = tid & 31, wid = tid >> 5;
    const int gid = lane >> 2, tig = lane & 3;
    const int x0 = blockIdx.x * 64, y0 = blockIdx.y * 2, b = blockIdx.z;
    const uint32_t sA_addr = smem_u32(sA);

    const unsigned* p0 = s0 + (size_t)b * c0 * HW;
    const unsigned* p1 = s1 ? s1 + (size_t)b * c1 * HW : p0;
    const unsigned* p2 = s2 ? s2 + (size_t)b * c2 * HW : p0;

    float acc[NT][4];
    #pragma unroll
    for (int nt = 0; nt < NT; ++nt)
        #pragma unroll
        for (int q = 0; q < 4; ++q) acc[nt][q] = 0.f;

    for (int ch = 0; ch < nch; ++ch) {
        const unsigned* wg = (const unsigned*)(wprep + (size_t)ch * 9 * 2 * OC * 16);
        for (int i = tid; i < 9 * 2 * OC * 8; i += 256) sW[i] = wg[i];
        for (int i = tid; i < 8 * 264; i += 256) {
            int cp = i / 264, pxh = i - cp * 264;
            int row = pxh / 66, col = pxh - row * 66;
            int gy = y0 - 1 + row, gx = x0 - 1 + col;
            unsigned wa = 0, wb = 0;
            if ((unsigned)gy < HH && (unsigned)gx < WW) {
                int goff = gy * WW + gx;
                int ca = ch * 16 + cp * 2;
                if (ca < cintot) {
                    const unsigned* pl = (ca < c0) ? p0 + (size_t)ca * HW
                                       : (ca < c0 + c1) ? p1 + (size_t)(ca - c0) * HW
                                       : p2 + (size_t)(ca - c0 - c1) * HW;
                    wa = pl[goff];
                }
                if (ca + 1 < cintot) {
                    const unsigned* ql = (ca + 1 < c0) ? p0 + (size_t)(ca + 1) * HW
                                       : (ca + 1 < c0 + c1) ? p1 + (size_t)(ca + 1 - c0) * HW
                                       : p2 + (size_t)(ca + 1 - c0 - c1) * HW;
                    wb = ql[goff];
                }
            }
            sA[pxh * 12 + cp]        = __byte_perm(wa, wb, 0x5410);  // hi pair
            sA[3168 + pxh * 12 + cp] = __byte_perm(wa, wb, 0x7632);  // lo pair
        }
        __syncthreads();

        #pragma unroll 1
        for (int tap = 0; tap < 9; ++tap) {
            int dy = tap / 3, dx = tap - dy * 3;
            int pxbase = ((wid >> 2) + dy) * 66 + (wid & 3) * 16 + dx;
            int px = pxbase + (lane & 15);
            uint32_t off = (uint32_t)(px * 12 + (lane >> 4) * 4) * 4;
            unsigned ah[4], al[4];
            ldmatrix_x4(ah, sA_addr + off);
            ldmatrix_x4(al, sA_addr + 12672 + off);
            const unsigned* wh = sW + (tap * 2 + 0) * (OC * 8);
            const unsigned* wl = sW + (tap * 2 + 1) * (OC * 8);
            #pragma unroll
            for (int nt = 0; nt < NT; ++nt) {
                int oc = nt * 8 + gid;
                unsigned b0h = wh[oc * 8 + tig], b1h = wh[oc * 8 + tig + 4];
                unsigned b0l = wl[oc * 8 + tig], b1l = wl[oc * 8 + tig + 4];
                mma16816(acc[nt], ah, b0h, b1h);   // Ah * Wh
                mma16816(acc[nt], ah, b0l, b1l);   // Ah * Wl
                mma16816(acc[nt], al, b0h, b1h);   // Al * Wh
            }
        }
        __syncthreads();
    }

    int gy = y0 + (wid >> 2);
    int gxA = x0 + (wid & 3) * 16 + gid;
    int gxB = gxA + 8;
    size_t rowoff = (size_t)gy * WW;
    #pragma unroll
    for (int nt = 0; nt < NT; ++nt) {
        int oc0 = nt * 8 + tig * 2;
        float v00 = acc[nt][0], v01 = acc[nt][1], v10 = acc[nt][2], v11 = acc[nt][3];
        if (ACT) {
            v00 = (v00 >= 0.f) ? v00 : 0.1f * v00;
            v01 = (v01 >= 0.f) ? v01 : 0.1f * v01;
            v10 = (v10 >= 0.f) ? v10 : 0.1f * v10;
            v11 = (v11 >= 0.f) ? v11 : 0.1f * v11;
        }
        size_t o0 = ((size_t)b * OC + oc0) * HW + rowoff;
        size_t o1 = o0 + HW;
        if (OUTF) {
            outF[o0 + gxA] = v00; outF[o1 + gxA] = v01;
            outF[o0 + gxB] = v10; outF[o1 + gxB] = v11;
        } else {
            outP[o0 + gxA] = pack_hl(v00); outP[o1 + gxA] = pack_hl(v01);
            outP[o0 + gxB] = pack_hl(v10); outP[o1 + gxB] = pack_hl(v11);
        }
    }
}

// ---------- conv7 scalar (16 -> 2, residual + leaky) ----------
__global__ void __launch_bounds__(256)
conv7_kernel(const float* __restrict__ in, const float* __restrict__ w,
             const float* __restrict__ biflow, int rc, float* __restrict__ out) {
    __shared__ float sw[288];
    int t = threadIdx.x;
    for (int i = t; i < 288; i += 256) sw[i] = w[i];   // FIX: full 288-weight staging
    __syncthreads();
    int idx = blockIdx.x * 256 + t;
    if (idx >= BB * HW) return;
    int p = idx % HW, b = idx / HW;
    int x = p % WW, y = p / WW;
    float a0 = 0.f, a1 = 0.f;
    const float* ib = in + (size_t)b * 16 * HW;
    for (int c = 0; c < 16; ++c) {
        const float* pl = ib + (size_t)c * HW;
        #pragma unroll
        for (int ky = 0; ky < 3; ++ky) {
            int yy = y + ky - 1;
            if ((unsigned)yy >= HH) continue;
            #pragma unroll
            for (int kx = 0; kx < 3; ++kx) {
                int xx = x + kx - 1;
                if ((unsigned)xx >= WW) continue;
                float v = pl[yy * WW + xx];
                a0 = fmaf(v, sw[c * 9 + ky * 3 + kx], a0);
                a1 = fmaf(v, sw[144 + c * 9 + ky * 3 + kx], a1);
            }
        }
    }
    a0 = (a0 >= 0.f) ? a0 : 0.1f * a0;
    a1 = (a1 >= 0.f) ? a1 : 0.1f * a1;
    size_t o = ((size_t)b * 4 + rc) * HW + p;
    out[o]      = a0 + biflow[o];
    out[o + HW] = a1 + biflow[o + HW];
}

// ---------- launch ----------
extern "C" void kernel_launch(void* const* d_in, const int* in_sizes, int n_in,
                              void* d_out, int out_size) {
    const float* f0 = (const float*)d_in[0];
    const float* f1 = (const float*)d_in[1];
    const float* bfp = (const float*)d_in[2];
    const float* ft = (const float*)d_in[3];
    const float* bt = (const float*)d_in[4];
    const float* Wt[7] = {(const float*)d_in[5], (const float*)d_in[6], (const float*)d_in[7],
                          (const float*)d_in[8], (const float*)d_in[9], (const float*)d_in[10],
                          (const float*)d_in[11]};
    float* out = (float*)d_out;

    float *biflow, *accA, *accB, *w0, *w1, *h6f;
    unsigned *w0p, *w1p, *ftp, *btp, *volp, *h1p, *h2p;
    __nv_bfloat16* wp;
    cudaGetSymbolAddress((void**)&biflow, g_biflow);
    cudaGetSymbolAddress((void**)&accA, g_accA);
    cudaGetSymbolAddress((void**)&accB, g_accB);
    cudaGetSymbolAddress((void**)&w0, g_warp0);
    cudaGetSymbolAddress((void**)&w1, g_warp1);
    cudaGetSymbolAddress((void**)&w0p, g_w0p);
    cudaGetSymbolAddress((void**)&w1p, g_w1p);
    cudaGetSymbolAddress((void**)&ftp, g_ftp);
    cudaGetSymbolAddress((void**)&btp, g_btp);
    cudaGetSymbolAddress((void**)&volp, g_volp);
    cudaGetSymbolAddress((void**)&h1p, g_h1p);
    cudaGetSymbolAddress((void**)&h2p, g_h2p);
    cudaGetSymbolAddress((void**)&h6f, g_h6f);
    cudaGetSymbolAddress((void**)&wp, g_wprep);

    const int SA = 6336 * 4;
    const int SM64 = SA + 9 * 2 * 64 * 8 * 4;   // 62208
    const int SM32 = SA + 9 * 2 * 32 * 8 * 4;   // 43776
    const int SM16 = SA + 9 * 2 * 16 * 8 * 4;   // 34560
    static bool attr = false;
    if (!attr) {
        cudaFuncSetAttribute(convM<64,0,0>, cudaFuncAttributeMaxDynamicSharedMemorySize, SM64);
        cudaFuncSetAttribute(convM<64,0,1>, cudaFuncAttributeMaxDynamicSharedMemorySize, SM64);
        attr = true;
    }

    const int O1 = 0, O2 = 184320, O3 = 258048, O4 = 331776, O5 = 368640, O6 = 387072;
    {
        int n1 = 10 * 288 * 64;
        prep_w_kernel<<<(n1 + 255) / 256, 256>>>(Wt[0], 64, 145, 10, wp + O1);
        int n2 = 4 * 288 * 64;
        prep_w_kernel<<<(n2 + 255) / 256, 256>>>(Wt[1], 64, 64, 4, wp + O2);
        prep_w_kernel<<<(n2 + 255) / 256, 256>>>(Wt[2], 64, 64, 4, wp + O3);
        int n4 = 4 * 288 * 32;
        prep_w_kernel<<<(n4 + 255) / 256, 256>>>(Wt[3], 32, 64, 4, wp + O4);
        int n5 = 2 * 288 * 32;
        prep_w_kernel<<<(n5 + 255) / 256, 256>>>(Wt[4], 32, 32, 2, wp + O5);
        int n6 = 2 * 288 * 16;
        prep_w_kernel<<<(n6 + 255) / 256, 256>>>(Wt[5], 16, 32, 2, wp + O6);
    }

    {
        int n = BB * 4 * HW;
        upsample_kernel<<<(n + 255) / 256, 256>>>(bfp, biflow);
        n = BB * 33 * HW;
        zero_kernel<<<(n + 255) / 256, 256>>>(accA, n);
        zero_kernel<<<(n + 255) / 256, 256>>>(accB, n);
        n = BB * HW;
        splat_kernel<<<(n + 255) / 256, 256>>>(f0, biflow, 0, accA);
        splat_kernel<<<(n + 255) / 256, 256>>>(f1, biflow, 2, accB);
        n = BB * 32 * HW;
        norm_kernel<<<(n + 255) / 256, 256>>>(accA, w0, w0p);
        norm_kernel<<<(n + 255) / 256, 256>>>(accB, w1, w1p);
        pack_kernel<<<(n + 255) / 256, 256>>>(ft, ftp, n);
        pack_kernel<<<(n + 255) / 256, 256>>>(bt, btp, n);
        dim3 g(HW / 256, BB);
        corr_kernel<<<g, 256>>>(w0, w1, volp);
    }

    dim3 gc(WW / 64, HH / 2, BB);
    int n7 = BB * HW;
    // forward branch
    convM<64,0,0><<<gc, 256, SM64>>>(w0p, 32, ftp, 32, volp, 81, 145, 10, wp + O1, h1p, nullptr);
    convM<64,0,0><<<gc, 256, SM64>>>(h1p, 64, nullptr, 0, nullptr, 0, 64, 4, wp + O2, h2p, nullptr);
    convM<64,0,1><<<gc, 256, SM64>>>(h2p, 64, nullptr, 0, nullptr, 0, 64, 4, wp + O3, h1p, nullptr);
    convM<32,0,0><<<gc, 256, SM32>>>(h1p, 64, nullptr, 0, nullptr, 0, 64, 4, wp + O4, h2p, nullptr);
    convM<32,0,0><<<gc, 256, SM32>>>(h2p, 32, nullptr, 0, nullptr, 0, 32, 2, wp + O5, h1p, nullptr);
    convM<16,1,0><<<gc, 256, SM16>>>(h1p, 32, nullptr, 0, nullptr, 0, 32, 2, wp + O6, nullptr, h6f);
    conv7_kernel<<<(n7 + 255) / 256, 256>>>(h6f, Wt[6], biflow, 0, out);
    // backward branch
    convM<64,0,0><<<gc, 256, SM64>>>(w1p, 32, btp, 32, volp, 81, 145, 10, wp + O1, h1p, nullptr);
    convM<64,0,0><<<gc, 256, SM64>>>(h1p, 64, nullptr, 0, nullptr, 0, 64, 4, wp + O2, h2p, nullptr);
    convM<64,0,1><<<gc, 256, SM64>>>(h2p, 64, nullptr, 0, nullptr, 0, 64, 4, wp + O3, h1p, nullptr);
    convM<32,0,0><<<gc, 256, SM32>>>(h1p, 64, nullptr, 0, nullptr, 0, 64, 4, wp + O4, h2p, nullptr);
    convM<32,0,0><<<gc, 256, SM32>>>(h2p, 32, nullptr, 0, nullptr, 0, 32, 2, wp + O5, h1p, nullptr);
    convM<16,1,0><<<gc, 256, SM16>>>(h1p, 32, nullptr, 0, nullptr, 0, 32, 2, wp + O6, nullptr, h6f);
    conv7_kernel<<<(n7 + 255) / 256, 256>>>(h6f, Wt[6], biflow, 2, out);
}

// round 16
// speedup vs baseline: 4.4052x; 2.1653x over previous
#include <cuda_runtime.h>
#include <cuda_bf16.h>
#include <cstdint>

#define BB 8
#define HH 192
#define WW 320
#define HW (HH*WW)
#define UPH (HH/2)
#define UPW (WW/2)

// ---------------- scratch ----------------
__device__ float    g_biflow[BB*4*HW];
__device__ float    g_accA[BB*33*HW];
__device__ float    g_accB[BB*33*HW];
__device__ float    g_warp0[BB*32*HW];
__device__ float    g_warp1[BB*32*HW];
// pair planes: word = (bf16(ch_even) | bf16(ch_odd)<<16), separate hi/lo tensors
__device__ unsigned g_w0h[BB*16*HW], g_w0l[BB*16*HW];
__device__ unsigned g_w1h[BB*16*HW], g_w1l[BB*16*HW];
__device__ unsigned g_fth[BB*16*HW], g_ftl[BB*16*HW];
__device__ unsigned g_bth[BB*16*HW], g_btl[BB*16*HW];
__device__ unsigned g_volh[BB*41*HW], g_voll[BB*41*HW];
__device__ unsigned g_h1h[BB*32*HW], g_h1l[BB*32*HW];
__device__ unsigned g_h2h[BB*32*HW], g_h2l[BB*32*HW];
__device__ unsigned g_h6h[BB*8*HW],  g_h6l[BB*8*HW];
__device__ __align__(16) __nv_bfloat16 g_wprep[460800];

// ---------------- helpers ----------------
__device__ __forceinline__ uint32_t smem_u32(const void* p) {
    uint32_t a;
    asm("{ .reg .u64 t; cvta.to.shared.u64 t, %1; cvt.u32.u64 %0, t; }" : "=r"(a) : "l"(p));
    return a;
}
__device__ __forceinline__ void cp4(uint32_t dst, const void* src, int sz) {
    asm volatile("cp.async.ca.shared.global [%0], [%1], 4, %2;" :: "r"(dst), "l"(src), "r"(sz) : "memory");
}
__device__ __forceinline__ void cp16(uint32_t dst, const void* src) {
    asm volatile("cp.async.cg.shared.global [%0], [%1], 16;" :: "r"(dst), "l"(src) : "memory");
}
#define CP_COMMIT() asm volatile("cp.async.commit_group;" ::: "memory")
#define CP_WAIT0()  asm volatile("cp.async.wait_group 0;" ::: "memory")

__device__ __forceinline__ void ldmatrix_x4(unsigned* r, uint32_t addr) {
    asm volatile("ldmatrix.sync.aligned.m8n8.x4.shared.b16 {%0,%1,%2,%3}, [%4];"
        : "=r"(r[0]), "=r"(r[1]), "=r"(r[2]), "=r"(r[3]) : "r"(addr));
}
__device__ __forceinline__ void mma16816(float* d, const unsigned* a, unsigned b0, unsigned b1) {
    asm volatile(
        "mma.sync.aligned.m16n8k16.row.col.f32.bf16.bf16.f32 "
        "{%0,%1,%2,%3}, {%4,%5,%6,%7}, {%8,%9}, {%0,%1,%2,%3};"
        : "+f"(d[0]), "+f"(d[1]), "+f"(d[2]), "+f"(d[3])
        : "r"(a[0]), "r"(a[1]), "r"(a[2]), "r"(a[3]), "r"(b0), "r"(b1));
}
__device__ __forceinline__ unsigned bf16hi_bits(float v) {
    return (unsigned)__bfloat16_as_ushort(__float2bfloat16(v));
}
// pack (hi_even|hi_odd<<16) and (lo_even|lo_odd<<16)
__device__ __forceinline__ void pack_pair(float v0, float v1, unsigned& hp, unsigned& lp) {
    unsigned h0 = bf16hi_bits(v0);
    float r0 = v0 - __uint_as_float(h0 << 16);
    unsigned l0 = bf16hi_bits(r0);
    unsigned h1 = bf16hi_bits(v1);
    float r1 = v1 - __uint_as_float(h1 << 16);
    unsigned l1 = bf16hi_bits(r1);
    hp = h0 | (h1 << 16);
    lp = l0 | (l1 << 16);
}

// ---------------- front-end ----------------
__global__ void zero_kernel(float* p, int n) {
    int i = blockIdx.x * 256 + threadIdx.x;
    if (i < n) p[i] = 0.f;
}
__global__ void upsample_kernel(const float* __restrict__ src, float* __restrict__ dst) {
    int idx = blockIdx.x * 256 + threadIdx.x;
    if (idx >= BB * 4 * HW) return;
    int x = idx % WW, y = (idx / WW) % HH, bc = idx / HW;
    float sx = fminf(fmaxf(0.5f * x - 0.25f, 0.f), (float)(UPW - 1));
    float sy = fminf(fmaxf(0.5f * y - 0.25f, 0.f), (float)(UPH - 1));
    int x0 = (int)floorf(sx), y0 = (int)floorf(sy);
    float fx = sx - x0, fy = sy - y0;
    int x1 = min(x0 + 1, UPW - 1), y1 = min(y0 + 1, UPH - 1);
    const float* p = src + (size_t)bc * (UPH * UPW);
    float v = (1.f - fy) * ((1.f - fx) * p[y0 * UPW + x0] + fx * p[y0 * UPW + x1])
            +          fy * ((1.f - fx) * p[y1 * UPW + x0] + fx * p[y1 * UPW + x1]);
    dst[idx] = 2.0f * v;
}
__global__ void splat_kernel(const float* __restrict__ feat, const float* __restrict__ flow4,
                             int fcoff, float* __restrict__ acc) {
    int idx = blockIdx.x * 256 + threadIdx.x;
    if (idx >= BB * HW) return;
    int x = idx % WW, y = (idx / WW) % HH, b = idx / HW;
    const float* fl = flow4 + ((size_t)b * 4 + fcoff) * HW + y * WW + x;
    float fx = x + fl[0], fy = y + fl[(size_t)HW];
    float x0f = floorf(fx), y0f = floorf(fy);
    float wx1 = fx - x0f, wy1 = fy - y0f, wx0 = 1.f - wx1, wy0 = 1.f - wy1;
    int ix0 = (int)x0f, iy0 = (int)y0f;
    int ixs[4] = {ix0, ix0 + 1, ix0, ix0 + 1};
    int iys[4] = {iy0, iy0, iy0 + 1, iy0 + 1};
    float ws[4] = {wx0 * wy0, wx1 * wy0, wx0 * wy1, wx1 * wy1};
    const float* fp = feat + (size_t)b * 32 * HW + y * WW + x;
    float* ap = acc + (size_t)b * 33 * HW;
    #pragma unroll
    for (int k = 0; k < 4; ++k) {
        int ix = ixs[k], iy = iys[k];
        if (ix < 0 || ix >= WW || iy < 0 || iy >= HH) continue;
        int off = iy * WW + ix;
        #pragma unroll
        for (int c = 0; c < 32; ++c)
            atomicAdd(ap + (size_t)c * HW + off, fp[(size_t)c * HW] * ws[k]);
        atomicAdd(ap + (size_t)32 * HW + off, ws[k]);
    }
}
// norm + fp32 warp planes + pair-packed hi/lo planes
__global__ void norm_pair_kernel(const float* __restrict__ acc, float* __restrict__ warp,
                                 unsigned* __restrict__ oh, unsigned* __restrict__ ol) {
    int idx = blockIdx.x * 256 + threadIdx.x;
    if (idx >= BB * 16 * HW) return;
    int p = idx % HW, pc = (idx / HW) % 16, b = idx / (16 * HW);
    float n = acc[((size_t)b * 33 + 32) * HW + p];
    n = (n == 0.f) ? 1.f : n;
    float v0 = acc[((size_t)b * 33 + 2 * pc) * HW + p] / n;
    float v1 = acc[((size_t)b * 33 + 2 * pc + 1) * HW + p] / n;
    warp[((size_t)b * 32 + 2 * pc) * HW + p] = v0;
    warp[((size_t)b * 32 + 2 * pc + 1) * HW + p] = v1;
    unsigned hp, lp;
    pack_pair(v0, v1, hp, lp);
    oh[idx] = hp; ol[idx] = lp;
}
__global__ void pack_pair_kernel(const float* __restrict__ src,
                                 unsigned* __restrict__ oh, unsigned* __restrict__ ol) {
    int idx = blockIdx.x * 256 + threadIdx.x;
    if (idx >= BB * 16 * HW) return;
    int p = idx % HW, pc = (idx / HW) % 16, b = idx / (16 * HW);
    float v0 = src[((size_t)b * 32 + 2 * pc) * HW + p];
    float v1 = src[((size_t)b * 32 + 2 * pc + 1) * HW + p];
    unsigned hp, lp;
    pack_pair(v0, v1, hp, lp);
    oh[idx] = hp; ol[idx] = lp;
}
__global__ void __launch_bounds__(256)
corr_kernel(const float* __restrict__ w0, const float* __restrict__ w1,
            unsigned* __restrict__ volh, unsigned* __restrict__ voll) {
    int p = blockIdx.x * 256 + threadIdx.x;
    int b = blockIdx.y;
    int x = p % WW, y = p / WW;
    const float* a0 = w0 + (size_t)b * 32 * HW + p;
    float a[32];
    #pragma unroll
    for (int c = 0; c < 32; ++c) a[c] = a0[(size_t)c * HW];
    const float* bb = w1 + (size_t)b * 32 * HW;
    unsigned* vh = volh + (size_t)b * 41 * HW + p;
    unsigned* vl = voll + (size_t)b * 41 * HW + p;
    float sprev = 0.f;
    int d = 0;
    #pragma unroll 1
    for (int dy = -4; dy <= 4; ++dy) {
        int yy = y + dy;
        #pragma unroll 1
        for (int dx = -4; dx <= 4; ++dx) {
            int xx = x + dx;
            float s = 0.f;
            if ((unsigned)yy < HH && (unsigned)xx < WW) {
                const float* bp = bb + yy * WW + xx;
                #pragma unroll
                for (int c = 0; c < 32; ++c) s = fmaf(a[c], bp[(size_t)c * HW], s);
                s *= (1.f / 32.f);
            }
            s = (s >= 0.f) ? s : 0.1f * s;
            if (d & 1) {
                unsigned hp, lp;
                pack_pair(sprev, s, hp, lp);
                vh[(size_t)(d >> 1) * HW] = hp;
                vl[(size_t)(d >> 1) * HW] = lp;
            } else sprev = s;
            ++d;
        }
    }
    unsigned hp, lp;
    pack_pair(sprev, 0.f, hp, lp);
    vh[(size_t)40 * HW] = hp;
    vl[(size_t)40 * HW] = lp;
}
// weight prep (unchanged layout): fp32 [oc][cin][9] -> bf16 [ch][tap][hf][oc][16k]
__global__ void prep_w_kernel(const float* __restrict__ Wt, int OC, int CIN, int nch,
                              __nv_bfloat16* __restrict__ dst) {
    int n = nch * 9 * 2 * OC * 16;
    int e = blockIdx.x * 256 + threadIdx.x;
    if (e >= n) return;
    int k = e & 15, r = e >> 4;
    int oc = r % OC; r /= OC;
    int hf = r & 1; r >>= 1;
    int tap = r % 9, ch = r / 9;
    int cin = ch * 16 + k;
    float w = (cin < CIN) ? Wt[((size_t)oc * CIN + cin) * 9 + tap] : 0.f;
    __nv_bfloat16 h = __float2bfloat16(w);
    dst[e] = hf ? __float2bfloat16(w - __bfloat162float(h)) : h;
}

// ---------------- HMMA conv v2: 4x64 tile, cp.async double-buffered ----------------
// sA: [2 buf][2 hf][396 px * 8 words], 32B records XOR-swizzled; sW: [tap][hf][OC][8 words]
#define NHALO 396
#define SA_HF 3168
#define SA_BUF 6336
#define SW_OFF 12672

template<int OC, int ACT>
__global__ void __launch_bounds__(256, 2)
convM(const unsigned* __restrict__ h0, const unsigned* __restrict__ l0, int c0p,
      const unsigned* __restrict__ h1, const unsigned* __restrict__ l1, int c1p,
      const unsigned* __restrict__ h2, const unsigned* __restrict__ l2, int c2p,
      int nch, const __nv_bfloat16* __restrict__ wprep,
      unsigned* __restrict__ outH, unsigned* __restrict__ outL) {
    constexpr int NT = OC / 8;
    extern __shared__ unsigned smem[];
    const int tid = threadIdx.x, lane = tid & 31, wid = tid >> 5;
    const int gid = lane >> 2, tig = lane & 3;
    const int x0 = blockIdx.x * 64, y0 = blockIdx.y * 4, b = blockIdx.z;
    const uint32_t sab = smem_u32(smem);
    const uint32_t swb = sab + SW_OFF * 4;
    unsigned* sWp = smem + SW_OFF;
    const int ctot = c0p + c1p + c2p;

    // stage activations for chunk ch into buffer buf (cp.async)
    auto issue_acts = [&](int ch, int buf) {
        uint32_t bbase = sab + (uint32_t)buf * SA_BUF * 4;
        #pragma unroll
        for (int cp = 0; cp < 8; ++cp) {
            int pc = ch * 8 + cp;
            const unsigned *ph, *pl;
            int szc = 4;
            if (pc < c0p)            { ph = h0 + ((size_t)b * c0p + pc) * HW;            pl = l0 + ((size_t)b * c0p + pc) * HW; }
            else if (pc < c0p + c1p) { ph = h1 + ((size_t)b * c1p + pc - c0p) * HW;      pl = l1 + ((size_t)b * c1p + pc - c0p) * HW; }
            else if (pc < ctot)      { ph = h2 + ((size_t)b * c2p + pc - c0p - c1p) * HW; pl = l2 + ((size_t)b * c2p + pc - c0p - c1p) * HW; }
            else                     { ph = h0; pl = l0; szc = 0; }
            #pragma unroll
            for (int s = 0; s < 2; ++s) {
                int j = tid + s * 256;
                if (j < NHALO) {
                    int hrow = j / 66, hcol = j - hrow * 66;
                    int gy = y0 - 1 + hrow, gx = x0 - 1 + hcol;
                    bool inb = ((unsigned)gy < HH) && ((unsigned)gx < WW);
                    int sz = inb ? szc : 0;
                    int off = inb ? gy * WW + gx : 0;
                    unsigned dw = (unsigned)j * 8 + (((cp >> 2) ^ ((j >> 2) & 1)) << 2) + (cp & 3);
                    cp4(bbase + dw * 4, ph + off, sz);
                    cp4(bbase + (dw + SA_HF) * 4, pl + off, sz);
                }
            }
        }
    };
    auto issue_wts = [&](int ch) {
        const uint4* wg = (const uint4*)(wprep + (size_t)ch * 9 * 2 * OC * 16);
        const int n16 = 9 * 2 * OC * 2;
        for (int i = tid; i < n16; i += 256) cp16(swb + (uint32_t)i * 16, wg + i);
    };

    float acc[NT][2][4];
    #pragma unroll
    for (int nt = 0; nt < NT; ++nt)
        #pragma unroll
        for (int m = 0; m < 2; ++m)
            #pragma unroll
            for (int q = 0; q < 4; ++q) acc[nt][m][q] = 0.f;

    issue_acts(0, 0);
    issue_wts(0);
    CP_COMMIT();
    CP_WAIT0();
    __syncthreads();

    int buf = 0;
    for (int ch = 0; ch < nch; ++ch) {
        if (ch + 1 < nch) { issue_acts(ch + 1, buf ^ 1); CP_COMMIT(); }

        uint32_t hb = sab + (uint32_t)buf * SA_BUF * 4;
        #pragma unroll 1
        for (int tap = 0; tap < 9; ++tap) {
            int dy = tap / 3, dx = tap - dy * 3;
            unsigned ah[2][4], al[2][4];
            #pragma unroll
            for (int m = 0; m < 2; ++m) {
                int p0 = wid * 32 + m * 16;
                int prow = p0 >> 6, pcol = p0 & 63;
                int px = (prow + dy) * 66 + (pcol + dx) + (lane & 15);
                unsigned a16 = ((unsigned)px << 1) + ((unsigned)(lane >> 4) ^ ((px >> 2) & 1));
                ldmatrix_x4(ah[m], hb + (a16 << 4));
                ldmatrix_x4(al[m], hb + SA_HF * 4 + (a16 << 4));
            }
            #pragma unroll
            for (int nt = 0; nt < NT; ++nt) {
                int oc = nt * 8 + gid;
                int whb = tap * OC * 16 + oc * 8;
                unsigned b0h = sWp[whb + tig],          b1h = sWp[whb + tig + 4];
                unsigned b0l = sWp[whb + OC * 8 + tig], b1l = sWp[whb + OC * 8 + tig + 4];
                #pragma unroll
                for (int m = 0; m < 2; ++m) {
                    mma16816(acc[nt][m], ah[m], b0h, b1h);
                    mma16816(acc[nt][m], ah[m], b0l, b1l);
                    mma16816(acc[nt][m], al[m], b0h, b1h);
                }
            }
        }
        __syncthreads();               // all warps done with sW (and current sA)
        if (ch + 1 < nch) { issue_wts(ch + 1); CP_COMMIT(); }
        CP_WAIT0();
        __syncthreads();
        buf ^= 1;
    }

    // epilogue: pair-packed hi/lo outputs
    #pragma unroll
    for (int nt = 0; nt < NT; ++nt) {
        int ocp = nt * 4 + tig;        // pair index (oc0 = nt*8 + 2*tig)
        #pragma unroll
        for (int m = 0; m < 2; ++m) {
            int p0 = wid * 32 + m * 16;
            int gy = y0 + (p0 >> 6);
            int colA = (p0 & 63) + gid;
            float v00 = acc[nt][m][0], v01 = acc[nt][m][1];
            float v10 = acc[nt][m][2], v11 = acc[nt][m][3];
            if (ACT) {
                v00 = (v00 >= 0.f) ? v00 : 0.1f * v00;
                v01 = (v01 >= 0.f) ? v01 : 0.1f * v01;
                v10 = (v10 >= 0.f) ? v10 : 0.1f * v10;
                v11 = (v11 >= 0.f) ? v11 : 0.1f * v11;
            }
            size_t base = ((size_t)b * (OC / 2) + ocp) * HW + (size_t)gy * WW + x0;
            unsigned hp, lp;
            pack_pair(v00, v01, hp, lp);
            outH[base + colA] = hp; outL[base + colA] = lp;
            pack_pair(v10, v11, hp, lp);
            outH[base + colA + 8] = hp; outL[base + colA + 8] = lp;
        }
    }
}

// ---------- conv7 scalar (16 -> 2 from pair planes, residual + leaky) ----------
__global__ void __launch_bounds__(256)
conv7_kernel(const unsigned* __restrict__ inh, const unsigned* __restrict__ inl,
             const float* __restrict__ w,
             const float* __restrict__ biflow, int rc, float* __restrict__ out) {
    __shared__ float sw[288];
    int t = threadIdx.x;
    for (int i = t; i < 288; i += 256) sw[i] = w[i];
    __syncthreads();
    int idx = blockIdx.x * 256 + t;
    if (idx >= BB * HW) return;
    int p = idx % HW, b = idx / HW;
    int x = p % WW, y = p / WW;
    float a0 = 0.f, a1 = 0.f;
    for (int cp = 0; cp < 8; ++cp) {
        const unsigned* ph = inh + ((size_t)b * 8 + cp) * HW;
        const unsigned* pl = inl + ((size_t)b * 8 + cp) * HW;
        #pragma unroll
        for (int ky = 0; ky < 3; ++ky) {
            int yy = y + ky - 1;
            if ((unsigned)yy >= HH) continue;
            #pragma unroll
            for (int kx = 0; kx < 3; ++kx) {
                int xx = x + kx - 1;
                if ((unsigned)xx >= WW) continue;
                int off = yy * WW + xx;
                unsigned hw = ph[off], lw = pl[off];
                float v0 = __uint_as_float(hw << 16) + __uint_as_float(lw << 16);
                float v1 = __uint_as_float(hw & 0xffff0000u) + __uint_as_float(lw & 0xffff0000u);
                int k = ky * 3 + kx;
                a0 = fmaf(v0, sw[(2 * cp) * 9 + k], a0);
                a0 = fmaf(v1, sw[(2 * cp + 1) * 9 + k], a0);
                a1 = fmaf(v0, sw[144 + (2 * cp) * 9 + k], a1);
                a1 = fmaf(v1, sw[144 + (2 * cp + 1) * 9 + k], a1);
            }
        }
    }
    a0 = (a0 >= 0.f) ? a0 : 0.1f * a0;
    a1 = (a1 >= 0.f) ? a1 : 0.1f * a1;
    size_t o = ((size_t)b * 4 + rc) * HW + p;
    out[o]      = a0 + biflow[o];
    out[o + HW] = a1 + biflow[o + HW];
}

// ---------------- launch ----------------
extern "C" void kernel_launch(void* const* d_in, const int* in_sizes, int n_in,
                              void* d_out, int out_size) {
    const float* f0 = (const float*)d_in[0];
    const float* f1 = (const float*)d_in[1];
    const float* bfp = (const float*)d_in[2];
    const float* ft = (const float*)d_in[3];
    const float* bt = (const float*)d_in[4];
    const float* Wt[7] = {(const float*)d_in[5], (const float*)d_in[6], (const float*)d_in[7],
                          (const float*)d_in[8], (const float*)d_in[9], (const float*)d_in[10],
                          (const float*)d_in[11]};
    float* out = (float*)d_out;

    float *biflow, *accA, *accB, *w0, *w1;
    unsigned *w0h, *w0l, *w1h, *w1l, *fth, *ftl, *bth, *btl, *volh, *voll;
    unsigned *h1h, *h1l, *h2h, *h2l, *h6h, *h6l;
    __nv_bfloat16* wp;
    cudaGetSymbolAddress((void**)&biflow, g_biflow);
    cudaGetSymbolAddress((void**)&accA, g_accA);
    cudaGetSymbolAddress((void**)&accB, g_accB);
    cudaGetSymbolAddress((void**)&w0, g_warp0);
    cudaGetSymbolAddress((void**)&w1, g_warp1);
    cudaGetSymbolAddress((void**)&w0h, g_w0h); cudaGetSymbolAddress((void**)&w0l, g_w0l);
    cudaGetSymbolAddress((void**)&w1h, g_w1h); cudaGetSymbolAddress((void**)&w1l, g_w1l);
    cudaGetSymbolAddress((void**)&fth, g_fth); cudaGetSymbolAddress((void**)&ftl, g_ftl);
    cudaGetSymbolAddress((void**)&bth, g_bth); cudaGetSymbolAddress((void**)&btl, g_btl);
    cudaGetSymbolAddress((void**)&volh, g_volh); cudaGetSymbolAddress((void**)&voll, g_voll);
    cudaGetSymbolAddress((void**)&h1h, g_h1h); cudaGetSymbolAddress((void**)&h1l, g_h1l);
    cudaGetSymbolAddress((void**)&h2h, g_h2h); cudaGetSymbolAddress((void**)&h2l, g_h2l);
    cudaGetSymbolAddress((void**)&h6h, g_h6h); cudaGetSymbolAddress((void**)&h6l, g_h6l);
    cudaGetSymbolAddress((void**)&wp, g_wprep);

    const int SM64 = (SW_OFF + 9 * 2 * 64 * 8) * 4;   // 87552
    const int SM32 = (SW_OFF + 9 * 2 * 32 * 8) * 4;   // 69120
    const int SM16 = (SW_OFF + 9 * 2 * 16 * 8) * 4;   // 59904
    static bool attr = false;
    if (!attr) {
        cudaFuncSetAttribute(convM<64,0>, cudaFuncAttributeMaxDynamicSharedMemorySize, SM64);
        cudaFuncSetAttribute(convM<64,1>, cudaFuncAttributeMaxDynamicSharedMemorySize, SM64);
        cudaFuncSetAttribute(convM<32,0>, cudaFuncAttributeMaxDynamicSharedMemorySize, SM32);
        cudaFuncSetAttribute(convM<16,0>, cudaFuncAttributeMaxDynamicSharedMemorySize, SM16);
        attr = true;
    }

    // ---- launches 0-4: front-end start ----
    {
        int n = BB * 4 * HW;
        upsample_kernel<<<(n + 255) / 256, 256>>>(bfp, biflow);            // 0
        n = BB * 33 * HW;
        zero_kernel<<<(n + 255) / 256, 256>>>(accA, n);                    // 1
        zero_kernel<<<(n + 255) / 256, 256>>>(accB, n);                    // 2
        n = BB * HW;
        splat_kernel<<<(n + 255) / 256, 256>>>(f0, biflow, 0, accA);       // 3
        splat_kernel<<<(n + 255) / 256, 256>>>(f1, biflow, 2, accB);       // 4
    }
    // ---- launch 5: DIAGNOSTIC dummy convM (profiled by ncu -s 5 -c 1).
    // Reads scratch (deterministic: device globals zero-init, then stable across
    // replays); writes h2 which real conv2 fully overwrites later.
    {
        dim3 gd(WW / 64, HH / 4, 1);
        convM<64,0><<<gd, 256, SM64>>>(h1h, h1l, 32, h1h, h1l, 0, h1h, h1l, 0,
                                       4, wp + 184320, h2h, h2l);          // 5
    }
    // ---- rest of front-end ----
    {
        int n = BB * 16 * HW;
        norm_pair_kernel<<<(n + 255) / 256, 256>>>(accA, w0, w0h, w0l);    // 6
        norm_pair_kernel<<<(n + 255) / 256, 256>>>(accB, w1, w1h, w1l);    // 7
        pack_pair_kernel<<<(n + 255) / 256, 256>>>(ft, fth, ftl);          // 8
        pack_pair_kernel<<<(n + 255) / 256, 256>>>(bt, bth, btl);          // 9
        dim3 g(HW / 256, BB);
        corr_kernel<<<g, 256>>>(w0, w1, volh, voll);                       // 10
    }
    // ---- weight prep ----
    const int O1 = 0, O2 = 184320, O3 = 258048, O4 = 331776, O5 = 368640, O6 = 387072;
    {
        int n1 = 10 * 288 * 64;
        prep_w_kernel<<<(n1 + 255) / 256, 256>>>(Wt[0], 64, 145, 10, wp + O1);
        int n2 = 4 * 288 * 64;
        prep_w_kernel<<<(n2 + 255) / 256, 256>>>(Wt[1], 64, 64, 4, wp + O2);
        prep_w_kernel<<<(n2 + 255) / 256, 256>>>(Wt[2], 64, 64, 4, wp + O3);
        int n4 = 4 * 288 * 32;
        prep_w_kernel<<<(n4 + 255) / 256, 256>>>(Wt[3], 32, 64, 4, wp + O4);
        int n5 = 2 * 288 * 32;
        prep_w_kernel<<<(n5 + 255) / 256, 256>>>(Wt[4], 32, 32, 2, wp + O5);
        int n6 = 2 * 288 * 16;
        prep_w_kernel<<<(n6 + 255) / 256, 256>>>(Wt[5], 16, 32, 2, wp + O6);
    }

    dim3 gc(WW / 64, HH / 4, BB);
    int n7 = BB * HW;
    // forward branch
    convM<64,0><<<gc, 256, SM64>>>(w0h, w0l, 16, fth, ftl, 16, volh, voll, 41, 10, wp + O1, h1h, h1l);
    convM<64,0><<<gc, 256, SM64>>>(h1h, h1l, 32, h1h, h1l, 0, h1h, h1l, 0, 4, wp + O2, h2h, h2l);
    convM<64,1><<<gc, 256, SM64>>>(h2h, h2l, 32, h2h, h2l, 0, h2h, h2l, 0, 4, wp + O3, h1h, h1l);
    convM<32,0><<<gc, 256, SM32>>>(h1h, h1l, 32, h1h, h1l, 0, h1h, h1l, 0, 4, wp + O4, h2h, h2l);
    convM<32,0><<<gc, 256, SM32>>>(h2h, h2l, 16, h2h, h2l, 0, h2h, h2l, 0, 2, wp + O5, h1h, h1l);
    convM<16,0><<<gc, 256, SM16>>>(h1h, h1l, 16, h1h, h1l, 0, h1h, h1l, 0, 2, wp + O6, h6h, h6l);
    conv7_kernel<<<(n7 + 255) / 256, 256>>>(h6h, h6l, Wt[6], biflow, 0, out);
    // backward branch
    convM<64,0><<<gc, 256, SM64>>>(w1h, w1l, 16, bth, btl, 16, volh, voll, 41, 10, wp + O1, h1h, h1l);
    convM<64,0><<<gc, 256, SM64>>>(h1h, h1l, 32, h1h, h1l, 0, h1h, h1l, 0, 4, wp + O2, h2h, h2l);
    convM<64,1><<<gc, 256, SM64>>>(h2h, h2l, 32, h2h, h2l, 0, h2h, h2l, 0, 4, wp + O3, h1h, h1l);
    convM<32,0><<<gc, 256, SM32>>>(h1h, h1l, 32, h1h, h1l, 0, h1h, h1l, 0, 4, wp + O4, h2h, h2l);
    convM<32,0><<<gc, 256, SM32>>>(h2h, h2l, 16, h2h, h2l, 0, h2h, h2l, 0, 2, wp + O5, h1h, h1l);
    convM<16,0><<<gc, 256, SM16>>>(h1h, h1l, 16, h1h, h1l, 0, h1h, h1l, 0, 2, wp + O6, h6h, h6l);
    conv7_kernel<<<(n7 + 255) / 256, 256>>>(h6h, h6l, Wt[6], biflow, 2, out);
}